// round 2
// baseline (speedup 1.0000x reference)
#include <cuda_runtime.h>
#include <cstdint>

#define NN 20000
#define EE 256000
#define HD 128
#define NRR 100
#define EPW 32   // edges per warp in sorted edge kernels

// ---------------- scratch (static device globals; no allocation) ----------------
__device__ float g_x0[NN * HD];        // embed[h]
__device__ float g_agg1[NN * HD];      // layer1 aggregation
__device__ float g_out1[NN * HD];      // layer1 output (relu)
__device__ float g_agg2[NN * 2 * HD];  // layer2 aggregation
__device__ float g_z[NN * HD];         // sampled latent
__device__ float g_hr[2048 * HD];      // decoder lhs
__device__ int   g_hist[NRR + 1];      // relation histogram / offsets
__device__ int   g_cursor[NRR];        // scatter cursors
__device__ int4  g_recs[EE];           // sorted edge records {src, dst, rel, norm}

// ---------------- helpers ----------------
__device__ __forceinline__ unsigned long long pk2(float x, float y) {
    unsigned long long r;
    asm("mov.b64 %0, {%1, %2};" : "=l"(r) : "f"(x), "f"(y));
    return r;
}
__device__ __forceinline__ void upk2(unsigned long long p, float& x, float& y) {
    asm("mov.b64 {%0, %1}, %2;" : "=f"(x), "=f"(y) : "l"(p));
}
__device__ __forceinline__ void fma2(unsigned long long& d, unsigned long long a, unsigned long long b) {
    asm("fma.rn.f32x2 %0, %1, %2, %0;" : "+l"(d) : "l"(a), "l"(b));
}
__device__ __forceinline__ void red_add_v4(float* addr, float a, float b, float c, float d) {
    asm volatile("red.global.add.v4.f32 [%0], {%1, %2, %3, %4};"
                 :: "l"(addr), "f"(a), "f"(b), "f"(c), "f"(d) : "memory");
}
__device__ __forceinline__ float softplus_f(float x) {
    return fmaxf(x, 0.f) + log1pf(expf(-fabsf(x)));
}

// ---------------- 1) gather x0 = embed[h], zero agg buffers + sort state ----------------
__global__ __launch_bounds__(256) void init_kernel(const int* __restrict__ h,
                                                   const float* __restrict__ embed) {
    int idx = blockIdx.x * blockDim.x + threadIdx.x;  // 0 .. N*256-1
    if (idx < NN * HD) {
        g_x0[idx] = embed[h[idx >> 7] * HD + (idx & 127)];
        g_agg1[idx] = 0.f;
    }
    g_agg2[idx] = 0.f;
    if (idx <= NRR) g_hist[idx] = 0;
}

// ---------------- sort pass A: relation histogram ----------------
__global__ __launch_bounds__(256) void hist_kernel(const int* __restrict__ et) {
    __shared__ int sh[NRR];
    int tid = threadIdx.x;
    if (tid < NRR) sh[tid] = 0;
    __syncthreads();
    int e = blockIdx.x * 256 + tid;
    atomicAdd(&sh[et[e]], 1);
    __syncthreads();
    if (tid < NRR && sh[tid]) atomicAdd(&g_hist[tid + 1], sh[tid]);
}

// ---------------- sort pass B: exclusive scan + cursor init (tiny) ----------------
__global__ void scan_kernel() {
    if (threadIdx.x == 0) {
        int acc = 0;
#pragma unroll 1
        for (int i = 0; i <= NRR; i++) { acc += g_hist[i]; g_hist[i] = acc; }
#pragma unroll 1
        for (int r = 0; r < NRR; r++) g_cursor[r] = g_hist[r];
    }
}

// ---------------- sort pass C: scatter packed records ----------------
__global__ __launch_bounds__(256) void scatter_kernel(const int* __restrict__ src,
                                                      const int* __restrict__ dst,
                                                      const int* __restrict__ et,
                                                      const float* __restrict__ norm) {
    int e = blockIdx.x * 256 + threadIdx.x;
    int r = et[e];
    int pos = atomicAdd(&g_cursor[r], 1);
    g_recs[pos] = make_int4(src[e], dst[e], r, __float_as_int(norm[e]));
}

// ---------------- 2) layer1 edge messages: warp walks EPW sorted edges ----------------
// lane l handles blocks 2l,2l+1 (output cols 4l..4l+3); W cached in regs per relation run
__global__ __launch_bounds__(256) void edge1_kernel(const float* __restrict__ W1) {
    int warp = (blockIdx.x * 256 + threadIdx.x) >> 5;
    int lane = threadIdx.x & 31;
    int e0 = warp * EPW;
    int cur = -1;
    float4 wa, wb;
#pragma unroll 1
    for (int e = e0; e < e0 + EPW; e++) {
        int4 rec = __ldg(&g_recs[e]);         // uniform broadcast load
        int s = rec.x, d = rec.y, r = rec.z;
        float nrm = __int_as_float(rec.w);
        if (r != cur) {                        // warp-uniform branch, rare
            const float4* w4 = (const float4*)(W1 + r * 256 + lane * 8);
            wa = __ldg(w4); wb = __ldg(w4 + 1);
            cur = r;
        }
        float4 xv = ((const float4*)(g_x0 + s * HD))[lane];
        float o0 = (xv.x * wa.x + xv.y * wa.z) * nrm;
        float o1 = (xv.x * wa.y + xv.y * wa.w) * nrm;
        float o2 = (xv.z * wb.x + xv.w * wb.z) * nrm;
        float o3 = (xv.z * wb.y + xv.w * wb.w) * nrm;
        red_add_v4(g_agg1 + d * HD + lane * 4, o0, o1, o2, o3);
    }
}

// ---------------- 3) self-loop layer1: out1 = relu(agg1 + x0 @ lw1 + b1) ----------------
__global__ __launch_bounds__(256) void selfloop1_kernel(const float* __restrict__ lw1,
                                                        const float* __restrict__ b1) {
    __shared__ float4 ws4[32][32];      // k-chunk 32 x 128 cols (16KB)
    __shared__ float xsh[8][4][33];
    int tid = threadIdx.x;
    int w = tid >> 5, lane = tid & 31;
    int row0 = blockIdx.x * 32 + w * 4;
    unsigned long long acc[4][2];
#pragma unroll
    for (int j = 0; j < 4; j++) { acc[j][0] = 0ULL; acc[j][1] = 0ULL; }
    const float4* lw4 = (const float4*)lw1;
    for (int kc = 0; kc < 4; kc++) {
#pragma unroll
        for (int it = 0; it < 4; it++) {
            int idx = tid + it * 256;
            int k = idx >> 5, c = idx & 31;
            ws4[k][c] = lw4[(kc * 32 + k) * 32 + c];
        }
#pragma unroll
        for (int j = 0; j < 4; j++)
            xsh[w][j][lane] = g_x0[(row0 + j) * HD + kc * 32 + lane];
        __syncthreads();
#pragma unroll
        for (int k = 0; k < 32; k++) {
            float4 wv = ws4[k][lane];
            unsigned long long wlo = pk2(wv.x, wv.y), whi = pk2(wv.z, wv.w);
#pragma unroll
            for (int j = 0; j < 4; j++) {
                float xv = xsh[w][j][k];
                unsigned long long x2 = pk2(xv, xv);
                fma2(acc[j][0], x2, wlo);
                fma2(acc[j][1], x2, whi);
            }
        }
        __syncthreads();
    }
    float4 bv = ((const float4*)b1)[lane];
#pragma unroll
    for (int j = 0; j < 4; j++) {
        int row = row0 + j;
        float4 av = ((const float4*)(g_agg1 + row * HD))[lane];
        float o0, o1, o2, o3;
        upk2(acc[j][0], o0, o1);
        upk2(acc[j][1], o2, o3);
        o0 = fmaxf(o0 + av.x + bv.x, 0.f);
        o1 = fmaxf(o1 + av.y + bv.y, 0.f);
        o2 = fmaxf(o2 + av.z + bv.z, 0.f);
        o3 = fmaxf(o3 + av.w + bv.w, 0.f);
        ((float4*)(g_out1 + row * HD))[lane] = make_float4(o0, o1, o2, o3);
    }
}

// ---------------- 4) layer2 edge messages: warp walks EPW sorted edges ----------------
// lane l handles blocks 2l,2l+1 (output cols 8l..8l+7); W cached in regs per relation run
__global__ __launch_bounds__(256) void edge2_kernel(const float* __restrict__ W2) {
    int warp = (blockIdx.x * 256 + threadIdx.x) >> 5;
    int lane = threadIdx.x & 31;
    int e0 = warp * EPW;
    int cur = -1;
    float4 wA, wB, wC, wD;
#pragma unroll 1
    for (int e = e0; e < e0 + EPW; e++) {
        int4 rec = __ldg(&g_recs[e]);
        int s = rec.x, d = rec.y, r = rec.z;
        float nrm = __int_as_float(rec.w);
        if (r != cur) {
            const float4* w4 = (const float4*)(W2 + r * 512 + lane * 16);
            wA = __ldg(w4);      // b=2l,   i=0, o0..3
            wB = __ldg(w4 + 1);  // b=2l,   i=1
            wC = __ldg(w4 + 2);  // b=2l+1, i=0
            wD = __ldg(w4 + 3);  // b=2l+1, i=1
            cur = r;
        }
        float4 xv = ((const float4*)(g_out1 + s * HD))[lane];
        float l0 = (xv.x * wA.x + xv.y * wB.x) * nrm;
        float l1 = (xv.x * wA.y + xv.y * wB.y) * nrm;
        float l2 = (xv.x * wA.z + xv.y * wB.z) * nrm;
        float l3 = (xv.x * wA.w + xv.y * wB.w) * nrm;
        float h0 = (xv.z * wC.x + xv.w * wD.x) * nrm;
        float h1 = (xv.z * wC.y + xv.w * wD.y) * nrm;
        float h2 = (xv.z * wC.z + xv.w * wD.z) * nrm;
        float h3 = (xv.z * wC.w + xv.w * wD.w) * nrm;
        float* base = g_agg2 + d * 2 * HD + lane * 8;
        red_add_v4(base, l0, l1, l2, l3);
        red_add_v4(base + 4, h0, h1, h2, h3);
    }
}

// ---------------- 5) self-loop layer2 + gaussian sample, fused ----------------
__global__ __launch_bounds__(256) void selfloop2_kernel(const float* __restrict__ lw2,
                                                        const float* __restrict__ b2,
                                                        const float* __restrict__ eps) {
    __shared__ float4 ws4[32][64];      // k-chunk 32 x 256 cols (32KB)
    __shared__ float xsh[8][4][33];
    int tid = threadIdx.x;
    int w = tid >> 5, lane = tid & 31;
    int row0 = blockIdx.x * 32 + w * 4;
    unsigned long long acc[4][4];
#pragma unroll
    for (int j = 0; j < 4; j++)
#pragma unroll
        for (int g = 0; g < 4; g++) acc[j][g] = 0ULL;
    const float4* lw4 = (const float4*)lw2;
    for (int kc = 0; kc < 4; kc++) {
#pragma unroll
        for (int it = 0; it < 8; it++) {
            int idx = tid + it * 256;
            int k = idx >> 6, c = idx & 63;
            ws4[k][c] = lw4[(kc * 32 + k) * 64 + c];
        }
#pragma unroll
        for (int j = 0; j < 4; j++)
            xsh[w][j][lane] = g_out1[(row0 + j) * HD + kc * 32 + lane];
        __syncthreads();
#pragma unroll
        for (int k = 0; k < 32; k++) {
            float4 w0 = ws4[k][lane];
            float4 w1 = ws4[k][32 + lane];
            unsigned long long wl0 = pk2(w0.x, w0.y), wh0 = pk2(w0.z, w0.w);
            unsigned long long wl1 = pk2(w1.x, w1.y), wh1 = pk2(w1.z, w1.w);
#pragma unroll
            for (int j = 0; j < 4; j++) {
                float xv = xsh[w][j][k];
                unsigned long long x2 = pk2(xv, xv);
                fma2(acc[j][0], x2, wl0);
                fma2(acc[j][1], x2, wh0);
                fma2(acc[j][2], x2, wl1);
                fma2(acc[j][3], x2, wh1);
            }
        }
        __syncthreads();
    }
    float4 b0 = ((const float4*)b2)[lane];
    float4 b1v = ((const float4*)b2)[32 + lane];
#pragma unroll
    for (int j = 0; j < 4; j++) {
        int row = row0 + j;
        float4 a0 = ((const float4*)(g_agg2 + row * 2 * HD))[lane];
        float4 a1 = ((const float4*)(g_agg2 + row * 2 * HD))[32 + lane];
        float m0, m1, m2, m3, v0, v1, v2, v3;
        upk2(acc[j][0], m0, m1);
        upk2(acc[j][1], m2, m3);
        upk2(acc[j][2], v0, v1);
        upk2(acc[j][3], v2, v3);
        m0 += a0.x + b0.x; m1 += a0.y + b0.y; m2 += a0.z + b0.z; m3 += a0.w + b0.w;
        v0 += a1.x + b1v.x; v1 += a1.y + b1v.y; v2 += a1.z + b1v.z; v3 += a1.w + b1v.w;
        float4 ev = ((const float4*)(eps + row * HD))[lane];
        float z0 = m0 + sqrtf(softplus_f(v0) + 1e-8f) * ev.x;
        float z1 = m1 + sqrtf(softplus_f(v1) + 1e-8f) * ev.y;
        float z2 = m2 + sqrtf(softplus_f(v2) + 1e-8f) * ev.z;
        float z3 = m3 + sqrtf(softplus_f(v3) + 1e-8f) * ev.w;
        ((float4*)(g_z + row * HD))[lane] = make_float4(z0, z1, z2, z3);
    }
}

// ---------------- 6) hr = z[head_ids] * w_rel[rel_ids] ----------------
__global__ __launch_bounds__(256) void hr_kernel(const int* __restrict__ head_ids,
                                                 const int* __restrict__ rel_ids,
                                                 const float* __restrict__ w_rel) {
    int idx = blockIdx.x * blockDim.x + threadIdx.x;  // 0 .. 2048*128-1
    int b = idx >> 7, c = idx & 127;
    g_hr[idx] = g_z[head_ids[b] * HD + c] * w_rel[rel_ids[b] * HD + c];
}

// ---------------- 7) decoder: scores = hr @ z^T  [2048 x 20000] ----------------
#define BM 128
#define BN 128
#define BK 32
__global__ __launch_bounds__(256) void decoder_kernel(float* __restrict__ out) {
    __shared__ float As[BK][BM + 4];
    __shared__ float Bs[BK][BN + 4];
    int tid = threadIdx.x;
    int row0 = blockIdx.y * BM;  // b-block (16 blocks, exact)
    int col0 = blockIdx.x * BN;  // n-block (157 blocks, last partial)
    int tr = tid >> 4, tc = tid & 15;
    unsigned long long acc[8][4];
#pragma unroll
    for (int i = 0; i < 8; i++)
#pragma unroll
        for (int p = 0; p < 4; p++) acc[i][p] = 0ULL;

    for (int kc = 0; kc < HD; kc += BK) {
#pragma unroll
        for (int it = 0; it < 4; it++) {
            int idx = tid + it * 256;      // 0..1023
            int r = idx >> 3, kq = idx & 7;
            float4 v = *(const float4*)(g_hr + (row0 + r) * HD + kc + kq * 4);
            As[kq * 4 + 0][r] = v.x; As[kq * 4 + 1][r] = v.y;
            As[kq * 4 + 2][r] = v.z; As[kq * 4 + 3][r] = v.w;
        }
#pragma unroll
        for (int it = 0; it < 4; it++) {
            int idx = tid + it * 256;
            int r = idx >> 3, kq = idx & 7;
            int n = col0 + r;
            float4 v = make_float4(0.f, 0.f, 0.f, 0.f);
            if (n < NN) v = *(const float4*)(g_z + n * HD + kc + kq * 4);
            Bs[kq * 4 + 0][r] = v.x; Bs[kq * 4 + 1][r] = v.y;
            Bs[kq * 4 + 2][r] = v.z; Bs[kq * 4 + 3][r] = v.w;
        }
        __syncthreads();
#pragma unroll
        for (int k = 0; k < BK; k++) {
            float4 a0 = *(float4*)&As[k][tr * 8];
            float4 a1 = *(float4*)&As[k][tr * 8 + 4];
            float4 bb0 = *(float4*)&Bs[k][tc * 8];
            float4 bb1 = *(float4*)&Bs[k][tc * 8 + 4];
            unsigned long long b2p[4] = {pk2(bb0.x, bb0.y), pk2(bb0.z, bb0.w),
                                         pk2(bb1.x, bb1.y), pk2(bb1.z, bb1.w)};
            float av[8] = {a0.x, a0.y, a0.z, a0.w, a1.x, a1.y, a1.z, a1.w};
#pragma unroll
            for (int i = 0; i < 8; i++) {
                unsigned long long a2 = pk2(av[i], av[i]);
                fma2(acc[i][0], a2, b2p[0]);
                fma2(acc[i][1], a2, b2p[1]);
                fma2(acc[i][2], a2, b2p[2]);
                fma2(acc[i][3], a2, b2p[3]);
            }
        }
        __syncthreads();
    }
#pragma unroll
    for (int i = 0; i < 8; i++) {
        int r = row0 + tr * 8 + i;
        int n = col0 + tc * 8;
        float o[8];
        upk2(acc[i][0], o[0], o[1]);
        upk2(acc[i][1], o[2], o[3]);
        upk2(acc[i][2], o[4], o[5]);
        upk2(acc[i][3], o[6], o[7]);
        float* orow = out + (size_t)r * NN;
        if (n + 3 < NN) *(float4*)(orow + n) = make_float4(o[0], o[1], o[2], o[3]);
        if (n + 7 < NN) *(float4*)(orow + n + 4) = make_float4(o[4], o[5], o[6], o[7]);
    }
}

// ---------------- launch ----------------
extern "C" void kernel_launch(void* const* d_in, const int* in_sizes, int n_in,
                              void* d_out, int out_size) {
    const int*   h        = (const int*)d_in[0];
    const int*   src      = (const int*)d_in[1];
    const int*   dst      = (const int*)d_in[2];
    const int*   etypes   = (const int*)d_in[3];
    const float* norm     = (const float*)d_in[4];
    const int*   head_ids = (const int*)d_in[5];
    const int*   rel_ids  = (const int*)d_in[6];
    const float* embed    = (const float*)d_in[7];
    const float* W1       = (const float*)d_in[8];
    const float* lw1      = (const float*)d_in[9];
    const float* b1       = (const float*)d_in[10];
    const float* W2       = (const float*)d_in[11];
    const float* lw2      = (const float*)d_in[12];
    const float* b2       = (const float*)d_in[13];
    const float* w_rel    = (const float*)d_in[14];
    const float* eps      = (const float*)d_in[15];
    float* out = (float*)d_out;

    init_kernel<<<(NN * 2 * HD) / 256, 256>>>(h, embed);
    hist_kernel<<<EE / 256, 256>>>(etypes);
    scan_kernel<<<1, 32>>>();
    scatter_kernel<<<EE / 256, 256>>>(src, dst, etypes, norm);
    edge1_kernel<<<EE / (EPW * 8), 256>>>(W1);
    selfloop1_kernel<<<NN / 32, 256>>>(lw1, b1);
    edge2_kernel<<<EE / (EPW * 8), 256>>>(W2);
    selfloop2_kernel<<<NN / 32, 256>>>(lw2, b2, eps);
    hr_kernel<<<(2048 * HD) / 256, 256>>>(head_ids, rel_ids, w_rel);
    dim3 dgrid((NN + BN - 1) / BN, 2048 / BM);
    decoder_kernel<<<dgrid, 256>>>(out);
}

// round 3
// speedup vs baseline: 1.1413x; 1.1413x over previous
#include <cuda_runtime.h>
#include <cstdint>

#define NN 20000
#define EE 256000
#define HD 128
#define NRR 100
#define EPW 16   // edges per warp in sorted edge kernels

// ---------------- scratch (static device globals; no allocation) ----------------
__device__ float g_x0[NN * HD];        // embed[h]
__device__ float g_agg1[NN * HD];      // layer1 aggregation
__device__ float g_out1[NN * HD];      // layer1 output (relu)
__device__ float g_agg2[NN * 2 * HD];  // layer2 aggregation
__device__ float g_z[NN * HD];         // sampled latent
__device__ float g_hr[2048 * HD];      // decoder lhs
__device__ int   g_hist[NRR + 1];      // relation histogram / offsets
__device__ int   g_cursor[NRR];        // scatter cursors
__device__ int4  g_recs[EE];           // sorted edge records {src, dst, rel, norm}

// ---------------- helpers ----------------
__device__ __forceinline__ unsigned long long pk2(float x, float y) {
    unsigned long long r;
    asm("mov.b64 %0, {%1, %2};" : "=l"(r) : "f"(x), "f"(y));
    return r;
}
__device__ __forceinline__ void upk2(unsigned long long p, float& x, float& y) {
    asm("mov.b64 {%0, %1}, %2;" : "=f"(x), "=f"(y) : "l"(p));
}
__device__ __forceinline__ void fma2(unsigned long long& d, unsigned long long a, unsigned long long b) {
    asm("fma.rn.f32x2 %0, %1, %2, %0;" : "+l"(d) : "l"(a), "l"(b));
}
__device__ __forceinline__ void red_add_v4(float* addr, float a, float b, float c, float d) {
    asm volatile("red.global.add.v4.f32 [%0], {%1, %2, %3, %4};"
                 :: "l"(addr), "f"(a), "f"(b), "f"(c), "f"(d) : "memory");
}
__device__ __forceinline__ float softplus_f(float x) {
    return fmaxf(x, 0.f) + log1pf(expf(-fabsf(x)));
}

// ---------------- 1) gather x0 = embed[h], zero agg buffers + sort state ----------------
__global__ __launch_bounds__(256) void init_kernel(const int* __restrict__ h,
                                                   const float* __restrict__ embed) {
    int idx = blockIdx.x * blockDim.x + threadIdx.x;  // 0 .. N*256-1
    if (idx < NN * HD) {
        g_x0[idx] = embed[h[idx >> 7] * HD + (idx & 127)];
        g_agg1[idx] = 0.f;
    }
    g_agg2[idx] = 0.f;
    if (idx <= NRR) g_hist[idx] = 0;
}

// ---------------- sort pass A: relation histogram (1024 edges/block) ----------------
__global__ __launch_bounds__(256) void hist_kernel(const int* __restrict__ et) {
    __shared__ int sh[NRR];
    int tid = threadIdx.x;
    if (tid < NRR) sh[tid] = 0;
    __syncthreads();
    int e0 = blockIdx.x * 1024 + tid;
#pragma unroll
    for (int j = 0; j < 4; j++) atomicAdd(&sh[et[e0 + j * 256]], 1);
    __syncthreads();
    if (tid < NRR && sh[tid]) atomicAdd(&g_hist[tid + 1], sh[tid]);
}

// ---------------- sort pass B: parallel inclusive scan of 101 values ----------------
__global__ __launch_bounds__(128) void scan_kernel() {
    __shared__ int s[128];
    int tid = threadIdx.x;
    s[tid] = (tid <= NRR) ? g_hist[tid] : 0;
    __syncthreads();
#pragma unroll
    for (int d = 1; d < 128; d <<= 1) {
        int v = (tid >= d) ? s[tid - d] : 0;
        __syncthreads();
        s[tid] += v;
        __syncthreads();
    }
    if (tid <= NRR) g_hist[tid] = s[tid];
    if (tid < NRR) g_cursor[tid] = s[tid];
}

// ---------------- sort pass C: block-aggregated scatter (1024 edges/block) ----------------
__global__ __launch_bounds__(256) void scatter_kernel(const int* __restrict__ src,
                                                      const int* __restrict__ dst,
                                                      const int* __restrict__ et,
                                                      const float* __restrict__ norm) {
    __shared__ int cnt[NRR];
    __shared__ int base[NRR];
    int tid = threadIdx.x;
    if (tid < NRR) cnt[tid] = 0;
    __syncthreads();
    int e0 = blockIdx.x * 1024 + tid;
    int r[4], s[4], d[4], nm[4];
#pragma unroll
    for (int j = 0; j < 4; j++) {
        int e = e0 + j * 256;
        r[j] = et[e]; s[j] = src[e]; d[j] = dst[e]; nm[j] = __float_as_int(norm[e]);
        atomicAdd(&cnt[r[j]], 1);
    }
    __syncthreads();
    if (tid < NRR) {
        int c = cnt[tid];
        base[tid] = c ? atomicAdd(&g_cursor[tid], c) : 0;
        cnt[tid] = 0;
    }
    __syncthreads();
#pragma unroll
    for (int j = 0; j < 4; j++) {
        int pos = base[r[j]] + atomicAdd(&cnt[r[j]], 1);
        g_recs[pos] = make_int4(s[j], d[j], r[j], nm[j]);
    }
}

// ---------------- 2) layer1 edge messages: warp walks EPW sorted edges ----------------
// lane l handles blocks 2l,2l+1 (output cols 4l..4l+3); W cached in regs per relation run
__global__ __launch_bounds__(256) void edge1_kernel(const float* __restrict__ W1) {
    int warp = (blockIdx.x * 256 + threadIdx.x) >> 5;
    int lane = threadIdx.x & 31;
    int e0 = warp * EPW;
    int cur = -1;
    float4 wa, wb;
    int4 rec = __ldg(&g_recs[e0]);
#pragma unroll 1
    for (int e = 0; e < EPW; e++) {
        int4 nrec = (e + 1 < EPW) ? __ldg(&g_recs[e0 + e + 1]) : rec;
        int s = rec.x, d = rec.y, r = rec.z;
        float nrm = __int_as_float(rec.w);
        float4 xv = ((const float4*)(g_x0 + s * HD))[lane];
        if (r != cur) {                        // warp-uniform branch, rare
            const float4* w4 = (const float4*)(W1 + r * 256 + lane * 8);
            wa = __ldg(w4); wb = __ldg(w4 + 1);
            cur = r;
        }
        float o0 = (xv.x * wa.x + xv.y * wa.z) * nrm;
        float o1 = (xv.x * wa.y + xv.y * wa.w) * nrm;
        float o2 = (xv.z * wb.x + xv.w * wb.z) * nrm;
        float o3 = (xv.z * wb.y + xv.w * wb.w) * nrm;
        red_add_v4(g_agg1 + d * HD + lane * 4, o0, o1, o2, o3);
        rec = nrec;
    }
}

// ---------------- 3) self-loop layer1: out1 = relu(agg1 + x0 @ lw1 + b1) ----------------
__global__ __launch_bounds__(256) void selfloop1_kernel(const float* __restrict__ lw1,
                                                        const float* __restrict__ b1) {
    __shared__ float4 ws4[32][32];      // k-chunk 32 x 128 cols (16KB)
    __shared__ float xsh[8][4][33];
    int tid = threadIdx.x;
    int w = tid >> 5, lane = tid & 31;
    int row0 = blockIdx.x * 32 + w * 4;
    unsigned long long acc[4][2];
#pragma unroll
    for (int j = 0; j < 4; j++) { acc[j][0] = 0ULL; acc[j][1] = 0ULL; }
    const float4* lw4 = (const float4*)lw1;
    for (int kc = 0; kc < 4; kc++) {
#pragma unroll
        for (int it = 0; it < 4; it++) {
            int idx = tid + it * 256;
            int k = idx >> 5, c = idx & 31;
            ws4[k][c] = lw4[(kc * 32 + k) * 32 + c];
        }
#pragma unroll
        for (int j = 0; j < 4; j++)
            xsh[w][j][lane] = g_x0[(row0 + j) * HD + kc * 32 + lane];
        __syncthreads();
#pragma unroll
        for (int k = 0; k < 32; k++) {
            float4 wv = ws4[k][lane];
            unsigned long long wlo = pk2(wv.x, wv.y), whi = pk2(wv.z, wv.w);
#pragma unroll
            for (int j = 0; j < 4; j++) {
                float xv = xsh[w][j][k];
                unsigned long long x2 = pk2(xv, xv);
                fma2(acc[j][0], x2, wlo);
                fma2(acc[j][1], x2, whi);
            }
        }
        __syncthreads();
    }
    float4 bv = ((const float4*)b1)[lane];
#pragma unroll
    for (int j = 0; j < 4; j++) {
        int row = row0 + j;
        float4 av = ((const float4*)(g_agg1 + row * HD))[lane];
        float o0, o1, o2, o3;
        upk2(acc[j][0], o0, o1);
        upk2(acc[j][1], o2, o3);
        o0 = fmaxf(o0 + av.x + bv.x, 0.f);
        o1 = fmaxf(o1 + av.y + bv.y, 0.f);
        o2 = fmaxf(o2 + av.z + bv.z, 0.f);
        o3 = fmaxf(o3 + av.w + bv.w, 0.f);
        ((float4*)(g_out1 + row * HD))[lane] = make_float4(o0, o1, o2, o3);
    }
}

// ---------------- 4) layer2 edge messages: warp walks EPW sorted edges ----------------
// lane l handles blocks 2l,2l+1 (output cols 8l..8l+7); W cached in regs per relation run
__global__ __launch_bounds__(256) void edge2_kernel(const float* __restrict__ W2) {
    int warp = (blockIdx.x * 256 + threadIdx.x) >> 5;
    int lane = threadIdx.x & 31;
    int e0 = warp * EPW;
    int cur = -1;
    float4 wA, wB, wC, wD;
    int4 rec = __ldg(&g_recs[e0]);
#pragma unroll 1
    for (int e = 0; e < EPW; e++) {
        int4 nrec = (e + 1 < EPW) ? __ldg(&g_recs[e0 + e + 1]) : rec;
        int s = rec.x, d = rec.y, r = rec.z;
        float nrm = __int_as_float(rec.w);
        float4 xv = ((const float4*)(g_out1 + s * HD))[lane];
        if (r != cur) {
            const float4* w4 = (const float4*)(W2 + r * 512 + lane * 16);
            wA = __ldg(w4);      // b=2l,   i=0, o0..3
            wB = __ldg(w4 + 1);  // b=2l,   i=1
            wC = __ldg(w4 + 2);  // b=2l+1, i=0
            wD = __ldg(w4 + 3);  // b=2l+1, i=1
            cur = r;
        }
        float l0 = (xv.x * wA.x + xv.y * wB.x) * nrm;
        float l1 = (xv.x * wA.y + xv.y * wB.y) * nrm;
        float l2 = (xv.x * wA.z + xv.y * wB.z) * nrm;
        float l3 = (xv.x * wA.w + xv.y * wB.w) * nrm;
        float h0 = (xv.z * wC.x + xv.w * wD.x) * nrm;
        float h1 = (xv.z * wC.y + xv.w * wD.y) * nrm;
        float h2 = (xv.z * wC.z + xv.w * wD.z) * nrm;
        float h3 = (xv.z * wC.w + xv.w * wD.w) * nrm;
        float* base = g_agg2 + d * 2 * HD + lane * 8;
        red_add_v4(base, l0, l1, l2, l3);
        red_add_v4(base + 4, h0, h1, h2, h3);
        rec = nrec;
    }
}

// ---------------- 5) self-loop layer2 + gaussian sample, fused ----------------
__global__ __launch_bounds__(256) void selfloop2_kernel(const float* __restrict__ lw2,
                                                        const float* __restrict__ b2,
                                                        const float* __restrict__ eps) {
    __shared__ float4 ws4[32][64];      // k-chunk 32 x 256 cols (32KB)
    __shared__ float xsh[8][4][33];
    int tid = threadIdx.x;
    int w = tid >> 5, lane = tid & 31;
    int row0 = blockIdx.x * 32 + w * 4;
    unsigned long long acc[4][4];
#pragma unroll
    for (int j = 0; j < 4; j++)
#pragma unroll
        for (int g = 0; g < 4; g++) acc[j][g] = 0ULL;
    const float4* lw4 = (const float4*)lw2;
    for (int kc = 0; kc < 4; kc++) {
#pragma unroll
        for (int it = 0; it < 8; it++) {
            int idx = tid + it * 256;
            int k = idx >> 6, c = idx & 63;
            ws4[k][c] = lw4[(kc * 32 + k) * 64 + c];
        }
#pragma unroll
        for (int j = 0; j < 4; j++)
            xsh[w][j][lane] = g_out1[(row0 + j) * HD + kc * 32 + lane];
        __syncthreads();
#pragma unroll
        for (int k = 0; k < 32; k++) {
            float4 w0 = ws4[k][lane];
            float4 w1 = ws4[k][32 + lane];
            unsigned long long wl0 = pk2(w0.x, w0.y), wh0 = pk2(w0.z, w0.w);
            unsigned long long wl1 = pk2(w1.x, w1.y), wh1 = pk2(w1.z, w1.w);
#pragma unroll
            for (int j = 0; j < 4; j++) {
                float xv = xsh[w][j][k];
                unsigned long long x2 = pk2(xv, xv);
                fma2(acc[j][0], x2, wl0);
                fma2(acc[j][1], x2, wh0);
                fma2(acc[j][2], x2, wl1);
                fma2(acc[j][3], x2, wh1);
            }
        }
        __syncthreads();
    }
    float4 b0 = ((const float4*)b2)[lane];
    float4 b1v = ((const float4*)b2)[32 + lane];
#pragma unroll
    for (int j = 0; j < 4; j++) {
        int row = row0 + j;
        float4 a0 = ((const float4*)(g_agg2 + row * 2 * HD))[lane];
        float4 a1 = ((const float4*)(g_agg2 + row * 2 * HD))[32 + lane];
        float m0, m1, m2, m3, v0, v1, v2, v3;
        upk2(acc[j][0], m0, m1);
        upk2(acc[j][1], m2, m3);
        upk2(acc[j][2], v0, v1);
        upk2(acc[j][3], v2, v3);
        m0 += a0.x + b0.x; m1 += a0.y + b0.y; m2 += a0.z + b0.z; m3 += a0.w + b0.w;
        v0 += a1.x + b1v.x; v1 += a1.y + b1v.y; v2 += a1.z + b1v.z; v3 += a1.w + b1v.w;
        float4 ev = ((const float4*)(eps + row * HD))[lane];
        float z0 = m0 + sqrtf(softplus_f(v0) + 1e-8f) * ev.x;
        float z1 = m1 + sqrtf(softplus_f(v1) + 1e-8f) * ev.y;
        float z2 = m2 + sqrtf(softplus_f(v2) + 1e-8f) * ev.z;
        float z3 = m3 + sqrtf(softplus_f(v3) + 1e-8f) * ev.w;
        ((float4*)(g_z + row * HD))[lane] = make_float4(z0, z1, z2, z3);
    }
}

// ---------------- 6) hr = z[head_ids] * w_rel[rel_ids] ----------------
__global__ __launch_bounds__(256) void hr_kernel(const int* __restrict__ head_ids,
                                                 const int* __restrict__ rel_ids,
                                                 const float* __restrict__ w_rel) {
    int idx = blockIdx.x * blockDim.x + threadIdx.x;  // 0 .. 2048*128-1
    int b = idx >> 7, c = idx & 127;
    g_hr[idx] = g_z[head_ids[b] * HD + c] * w_rel[rel_ids[b] * HD + c];
}

// ---------------- 7) decoder: scores = hr @ z^T  [2048 x 20000] ----------------
#define BM 128
#define BN 128
#define BK 32
__global__ __launch_bounds__(256) void decoder_kernel(float* __restrict__ out) {
    __shared__ float As[BK][BM + 4];
    __shared__ float Bs[BK][BN + 4];
    int tid = threadIdx.x;
    int row0 = blockIdx.y * BM;  // b-block (16 blocks, exact)
    int col0 = blockIdx.x * BN;  // n-block (157 blocks, last partial)
    int tr = tid >> 4, tc = tid & 15;
    unsigned long long acc[8][4];
#pragma unroll
    for (int i = 0; i < 8; i++)
#pragma unroll
        for (int p = 0; p < 4; p++) acc[i][p] = 0ULL;

    for (int kc = 0; kc < HD; kc += BK) {
#pragma unroll
        for (int it = 0; it < 4; it++) {
            int idx = tid + it * 256;      // 0..1023
            int r = idx >> 3, kq = idx & 7;
            float4 v = *(const float4*)(g_hr + (row0 + r) * HD + kc + kq * 4);
            As[kq * 4 + 0][r] = v.x; As[kq * 4 + 1][r] = v.y;
            As[kq * 4 + 2][r] = v.z; As[kq * 4 + 3][r] = v.w;
        }
#pragma unroll
        for (int it = 0; it < 4; it++) {
            int idx = tid + it * 256;
            int r = idx >> 3, kq = idx & 7;
            int n = col0 + r;
            float4 v = make_float4(0.f, 0.f, 0.f, 0.f);
            if (n < NN) v = *(const float4*)(g_z + n * HD + kc + kq * 4);
            Bs[kq * 4 + 0][r] = v.x; Bs[kq * 4 + 1][r] = v.y;
            Bs[kq * 4 + 2][r] = v.z; Bs[kq * 4 + 3][r] = v.w;
        }
        __syncthreads();
#pragma unroll
        for (int k = 0; k < BK; k++) {
            float4 a0 = *(float4*)&As[k][tr * 8];
            float4 a1 = *(float4*)&As[k][tr * 8 + 4];
            float4 bb0 = *(float4*)&Bs[k][tc * 8];
            float4 bb1 = *(float4*)&Bs[k][tc * 8 + 4];
            unsigned long long b2p[4] = {pk2(bb0.x, bb0.y), pk2(bb0.z, bb0.w),
                                         pk2(bb1.x, bb1.y), pk2(bb1.z, bb1.w)};
            float av[8] = {a0.x, a0.y, a0.z, a0.w, a1.x, a1.y, a1.z, a1.w};
#pragma unroll
            for (int i = 0; i < 8; i++) {
                unsigned long long a2 = pk2(av[i], av[i]);
                fma2(acc[i][0], a2, b2p[0]);
                fma2(acc[i][1], a2, b2p[1]);
                fma2(acc[i][2], a2, b2p[2]);
                fma2(acc[i][3], a2, b2p[3]);
            }
        }
        __syncthreads();
    }
#pragma unroll
    for (int i = 0; i < 8; i++) {
        int r = row0 + tr * 8 + i;
        int n = col0 + tc * 8;
        float o[8];
        upk2(acc[i][0], o[0], o[1]);
        upk2(acc[i][1], o[2], o[3]);
        upk2(acc[i][2], o[4], o[5]);
        upk2(acc[i][3], o[6], o[7]);
        float* orow = out + (size_t)r * NN;
        if (n + 3 < NN) *(float4*)(orow + n) = make_float4(o[0], o[1], o[2], o[3]);
        if (n + 7 < NN) *(float4*)(orow + n + 4) = make_float4(o[4], o[5], o[6], o[7]);
    }
}

// ---------------- launch ----------------
extern "C" void kernel_launch(void* const* d_in, const int* in_sizes, int n_in,
                              void* d_out, int out_size) {
    const int*   h        = (const int*)d_in[0];
    const int*   src      = (const int*)d_in[1];
    const int*   dst      = (const int*)d_in[2];
    const int*   etypes   = (const int*)d_in[3];
    const float* norm     = (const float*)d_in[4];
    const int*   head_ids = (const int*)d_in[5];
    const int*   rel_ids  = (const int*)d_in[6];
    const float* embed    = (const float*)d_in[7];
    const float* W1       = (const float*)d_in[8];
    const float* lw1      = (const float*)d_in[9];
    const float* b1       = (const float*)d_in[10];
    const float* W2       = (const float*)d_in[11];
    const float* lw2      = (const float*)d_in[12];
    const float* b2       = (const float*)d_in[13];
    const float* w_rel    = (const float*)d_in[14];
    const float* eps      = (const float*)d_in[15];
    float* out = (float*)d_out;

    init_kernel<<<(NN * 2 * HD) / 256, 256>>>(h, embed);
    hist_kernel<<<EE / 1024, 256>>>(etypes);
    scan_kernel<<<1, 128>>>();
    scatter_kernel<<<EE / 1024, 256>>>(src, dst, etypes, norm);
    edge1_kernel<<<EE / (EPW * 8), 256>>>(W1);
    selfloop1_kernel<<<NN / 32, 256>>>(lw1, b1);
    edge2_kernel<<<EE / (EPW * 8), 256>>>(W2);
    selfloop2_kernel<<<NN / 32, 256>>>(lw2, b2, eps);
    hr_kernel<<<(2048 * HD) / 256, 256>>>(head_ids, rel_ids, w_rel);
    dim3 dgrid((NN + BN - 1) / BN, 2048 / BM);
    decoder_kernel<<<dgrid, 256>>>(out);
}

// round 6
// speedup vs baseline: 1.6983x; 1.4880x over previous
#include <cuda_runtime.h>
#include <cuda_bf16.h>
#include <cstdint>

#define NN 20000
#define EE 256000
#define HD 128
#define NRR 100
#define EPW 16   // edges per warp in sorted edge kernels

// ---------------- scratch (static device globals; no allocation) ----------------
__device__ float g_x0[NN * HD];        // embed[h]
__device__ float g_agg1[NN * HD];      // layer1 aggregation
__device__ float g_out1[NN * HD];      // layer1 output (relu)
__device__ float g_agg2[NN * 2 * HD];  // layer2 aggregation
__device__ float g_z[NN * HD];         // sampled latent (fp32, for hr gather)
__device__ __nv_bfloat16 g_zhi[NN * HD];
__device__ __nv_bfloat16 g_zlo[NN * HD];
__device__ __nv_bfloat16 g_hrhi[2048 * HD];
__device__ __nv_bfloat16 g_hrlo[2048 * HD];
__device__ int   g_hist[NRR + 1];      // relation histogram / offsets
__device__ int   g_cursor[NRR];        // scatter cursors
__device__ int4  g_recs[EE];           // sorted edge records {src, dst, rel, norm}

// ---------------- helpers ----------------
__device__ __forceinline__ unsigned long long pk2(float x, float y) {
    unsigned long long r;
    asm("mov.b64 %0, {%1, %2};" : "=l"(r) : "f"(x), "f"(y));
    return r;
}
__device__ __forceinline__ void upk2(unsigned long long p, float& x, float& y) {
    asm("mov.b64 {%0, %1}, %2;" : "=f"(x), "=f"(y) : "l"(p));
}
__device__ __forceinline__ void fma2(unsigned long long& d, unsigned long long a, unsigned long long b) {
    asm("fma.rn.f32x2 %0, %1, %2, %0;" : "+l"(d) : "l"(a), "l"(b));
}
__device__ __forceinline__ void red_add_v4(float* addr, float a, float b, float c, float d) {
    asm volatile("red.global.add.v4.f32 [%0], {%1, %2, %3, %4};"
                 :: "l"(addr), "f"(a), "f"(b), "f"(c), "f"(d) : "memory");
}
__device__ __forceinline__ float softplus_f(float x) {
    return fmaxf(x, 0.f) + log1pf(expf(-fabsf(x)));
}
__device__ __forceinline__ uint32_t smem_to_u32(const void* p) {
    uint32_t a;
    asm("{ .reg .u64 t; cvta.to.shared.u64 t, %1; cvt.u32.u64 %0, t; }" : "=r"(a) : "l"(p));
    return a;
}
__device__ __forceinline__ void ldm_x4(uint32_t& r0, uint32_t& r1, uint32_t& r2, uint32_t& r3,
                                       uint32_t addr) {
    asm volatile("ldmatrix.sync.aligned.m8n8.x4.shared.b16 {%0,%1,%2,%3}, [%4];"
                 : "=r"(r0), "=r"(r1), "=r"(r2), "=r"(r3) : "r"(addr));
}
__device__ __forceinline__ void ldm_x2(uint32_t& r0, uint32_t& r1, uint32_t addr) {
    asm volatile("ldmatrix.sync.aligned.m8n8.x2.shared.b16 {%0,%1}, [%2];"
                 : "=r"(r0), "=r"(r1) : "r"(addr));
}
__device__ __forceinline__ void mma_bf16(float* c, uint32_t a0, uint32_t a1, uint32_t a2,
                                         uint32_t a3, uint32_t b0, uint32_t b1) {
    asm volatile(
        "mma.sync.aligned.m16n8k16.row.col.f32.bf16.bf16.f32 "
        "{%0,%1,%2,%3}, {%4,%5,%6,%7}, {%8,%9}, {%0,%1,%2,%3};"
        : "+f"(c[0]), "+f"(c[1]), "+f"(c[2]), "+f"(c[3])
        : "r"(a0), "r"(a1), "r"(a2), "r"(a3), "r"(b0), "r"(b1));
}

// ---------------- 1) gather x0 = embed[h], zero agg buffers + sort state ----------------
__global__ __launch_bounds__(256) void init_kernel(const int* __restrict__ h,
                                                   const float* __restrict__ embed) {
    int idx = blockIdx.x * blockDim.x + threadIdx.x;  // 0 .. N*256-1
    if (idx < NN * HD) {
        g_x0[idx] = embed[h[idx >> 7] * HD + (idx & 127)];
        g_agg1[idx] = 0.f;
    }
    g_agg2[idx] = 0.f;
    if (idx <= NRR) g_hist[idx] = 0;
}

// ---------------- sort pass A: relation histogram (1024 edges/block) ----------------
__global__ __launch_bounds__(256) void hist_kernel(const int* __restrict__ et) {
    __shared__ int sh[NRR];
    int tid = threadIdx.x;
    if (tid < NRR) sh[tid] = 0;
    __syncthreads();
    int e0 = blockIdx.x * 1024 + tid;
#pragma unroll
    for (int j = 0; j < 4; j++) atomicAdd(&sh[et[e0 + j * 256]], 1);
    __syncthreads();
    if (tid < NRR && sh[tid]) atomicAdd(&g_hist[tid + 1], sh[tid]);
}

// ---------------- sort pass B: parallel inclusive scan of 101 values ----------------
__global__ __launch_bounds__(128) void scan_kernel() {
    __shared__ int s[128];
    int tid = threadIdx.x;
    s[tid] = (tid <= NRR) ? g_hist[tid] : 0;
    __syncthreads();
#pragma unroll
    for (int d = 1; d < 128; d <<= 1) {
        int v = (tid >= d) ? s[tid - d] : 0;
        __syncthreads();
        s[tid] += v;
        __syncthreads();
    }
    if (tid <= NRR) g_hist[tid] = s[tid];
    if (tid < NRR) g_cursor[tid] = s[tid];
}

// ---------------- sort pass C: block-aggregated scatter (1024 edges/block) ----------------
__global__ __launch_bounds__(256) void scatter_kernel(const int* __restrict__ src,
                                                      const int* __restrict__ dst,
                                                      const int* __restrict__ et,
                                                      const float* __restrict__ norm) {
    __shared__ int cnt[NRR];
    __shared__ int base[NRR];
    int tid = threadIdx.x;
    if (tid < NRR) cnt[tid] = 0;
    __syncthreads();
    int e0 = blockIdx.x * 1024 + tid;
    int r[4], s[4], d[4], nm[4];
#pragma unroll
    for (int j = 0; j < 4; j++) {
        int e = e0 + j * 256;
        r[j] = et[e]; s[j] = src[e]; d[j] = dst[e]; nm[j] = __float_as_int(norm[e]);
        atomicAdd(&cnt[r[j]], 1);
    }
    __syncthreads();
    if (tid < NRR) {
        int c = cnt[tid];
        base[tid] = c ? atomicAdd(&g_cursor[tid], c) : 0;
        cnt[tid] = 0;
    }
    __syncthreads();
#pragma unroll
    for (int j = 0; j < 4; j++) {
        int pos = base[r[j]] + atomicAdd(&cnt[r[j]], 1);
        g_recs[pos] = make_int4(s[j], d[j], r[j], nm[j]);
    }
}

// ---------------- 2) layer1 edge messages: warp walks EPW sorted edges ----------------
__global__ __launch_bounds__(256) void edge1_kernel(const float* __restrict__ W1) {
    int warp = (blockIdx.x * 256 + threadIdx.x) >> 5;
    int lane = threadIdx.x & 31;
    int e0 = warp * EPW;
    int cur = -1;
    float4 wa, wb;
    int4 rec = __ldg(&g_recs[e0]);
#pragma unroll 1
    for (int e = 0; e < EPW; e++) {
        int4 nrec = (e + 1 < EPW) ? __ldg(&g_recs[e0 + e + 1]) : rec;
        int s = rec.x, d = rec.y, r = rec.z;
        float nrm = __int_as_float(rec.w);
        float4 xv = ((const float4*)(g_x0 + s * HD))[lane];
        if (r != cur) {                        // warp-uniform branch, rare
            const float4* w4 = (const float4*)(W1 + r * 256 + lane * 8);
            wa = __ldg(w4); wb = __ldg(w4 + 1);
            cur = r;
        }
        float o0 = (xv.x * wa.x + xv.y * wa.z) * nrm;
        float o1 = (xv.x * wa.y + xv.y * wa.w) * nrm;
        float o2 = (xv.z * wb.x + xv.w * wb.z) * nrm;
        float o3 = (xv.z * wb.y + xv.w * wb.w) * nrm;
        red_add_v4(g_agg1 + d * HD + lane * 4, o0, o1, o2, o3);
        rec = nrec;
    }
}

// ---------------- 3) self-loop layer1: out1 = relu(agg1 + x0 @ lw1 + b1) ----------------
__global__ __launch_bounds__(256) void selfloop1_kernel(const float* __restrict__ lw1,
                                                        const float* __restrict__ b1) {
    __shared__ float4 ws4[32][32];
    __shared__ float xsh[8][4][33];
    int tid = threadIdx.x;
    int w = tid >> 5, lane = tid & 31;
    int row0 = blockIdx.x * 32 + w * 4;
    unsigned long long acc[4][2];
#pragma unroll
    for (int j = 0; j < 4; j++) { acc[j][0] = 0ULL; acc[j][1] = 0ULL; }
    const float4* lw4 = (const float4*)lw1;
    for (int kc = 0; kc < 4; kc++) {
#pragma unroll
        for (int it = 0; it < 4; it++) {
            int idx = tid + it * 256;
            int k = idx >> 5, c = idx & 31;
            ws4[k][c] = lw4[(kc * 32 + k) * 32 + c];
        }
#pragma unroll
        for (int j = 0; j < 4; j++)
            xsh[w][j][lane] = g_x0[(row0 + j) * HD + kc * 32 + lane];
        __syncthreads();
#pragma unroll
        for (int k = 0; k < 32; k++) {
            float4 wv = ws4[k][lane];
            unsigned long long wlo = pk2(wv.x, wv.y), whi = pk2(wv.z, wv.w);
#pragma unroll
            for (int j = 0; j < 4; j++) {
                float xv = xsh[w][j][k];
                unsigned long long x2 = pk2(xv, xv);
                fma2(acc[j][0], x2, wlo);
                fma2(acc[j][1], x2, whi);
            }
        }
        __syncthreads();
    }
    float4 bv = ((const float4*)b1)[lane];
#pragma unroll
    for (int j = 0; j < 4; j++) {
        int row = row0 + j;
        float4 av = ((const float4*)(g_agg1 + row * HD))[lane];
        float o0, o1, o2, o3;
        upk2(acc[j][0], o0, o1);
        upk2(acc[j][1], o2, o3);
        o0 = fmaxf(o0 + av.x + bv.x, 0.f);
        o1 = fmaxf(o1 + av.y + bv.y, 0.f);
        o2 = fmaxf(o2 + av.z + bv.z, 0.f);
        o3 = fmaxf(o3 + av.w + bv.w, 0.f);
        ((float4*)(g_out1 + row * HD))[lane] = make_float4(o0, o1, o2, o3);
    }
}

// ---------------- 4) layer2 edge messages: warp walks EPW sorted edges ----------------
__global__ __launch_bounds__(256) void edge2_kernel(const float* __restrict__ W2) {
    int warp = (blockIdx.x * 256 + threadIdx.x) >> 5;
    int lane = threadIdx.x & 31;
    int e0 = warp * EPW;
    int cur = -1;
    float4 wA, wB, wC, wD;
    int4 rec = __ldg(&g_recs[e0]);
#pragma unroll 1
    for (int e = 0; e < EPW; e++) {
        int4 nrec = (e + 1 < EPW) ? __ldg(&g_recs[e0 + e + 1]) : rec;
        int s = rec.x, d = rec.y, r = rec.z;
        float nrm = __int_as_float(rec.w);
        float4 xv = ((const float4*)(g_out1 + s * HD))[lane];
        if (r != cur) {
            const float4* w4 = (const float4*)(W2 + r * 512 + lane * 16);
            wA = __ldg(w4);
            wB = __ldg(w4 + 1);
            wC = __ldg(w4 + 2);
            wD = __ldg(w4 + 3);
            cur = r;
        }
        float l0 = (xv.x * wA.x + xv.y * wB.x) * nrm;
        float l1 = (xv.x * wA.y + xv.y * wB.y) * nrm;
        float l2 = (xv.x * wA.z + xv.y * wB.z) * nrm;
        float l3 = (xv.x * wA.w + xv.y * wB.w) * nrm;
        float h0 = (xv.z * wC.x + xv.w * wD.x) * nrm;
        float h1 = (xv.z * wC.y + xv.w * wD.y) * nrm;
        float h2 = (xv.z * wC.z + xv.w * wD.z) * nrm;
        float h3 = (xv.z * wC.w + xv.w * wD.w) * nrm;
        float* base = g_agg2 + d * 2 * HD + lane * 8;
        red_add_v4(base, l0, l1, l2, l3);
        red_add_v4(base + 4, h0, h1, h2, h3);
        rec = nrec;
    }
}

// ---------------- 5) self-loop layer2 + gaussian sample + bf16 split, fused ----------------
__global__ __launch_bounds__(256) void selfloop2_kernel(const float* __restrict__ lw2,
                                                        const float* __restrict__ b2,
                                                        const float* __restrict__ eps) {
    __shared__ float4 ws4[32][64];
    __shared__ float xsh[8][4][33];
    int tid = threadIdx.x;
    int w = tid >> 5, lane = tid & 31;
    int row0 = blockIdx.x * 32 + w * 4;
    unsigned long long acc[4][4];
#pragma unroll
    for (int j = 0; j < 4; j++)
#pragma unroll
        for (int g = 0; g < 4; g++) acc[j][g] = 0ULL;
    const float4* lw4 = (const float4*)lw2;
    for (int kc = 0; kc < 4; kc++) {
#pragma unroll
        for (int it = 0; it < 8; it++) {
            int idx = tid + it * 256;
            int k = idx >> 6, c = idx & 63;
            ws4[k][c] = lw4[(kc * 32 + k) * 64 + c];
        }
#pragma unroll
        for (int j = 0; j < 4; j++)
            xsh[w][j][lane] = g_out1[(row0 + j) * HD + kc * 32 + lane];
        __syncthreads();
#pragma unroll
        for (int k = 0; k < 32; k++) {
            float4 w0 = ws4[k][lane];
            float4 w1 = ws4[k][32 + lane];
            unsigned long long wl0 = pk2(w0.x, w0.y), wh0 = pk2(w0.z, w0.w);
            unsigned long long wl1 = pk2(w1.x, w1.y), wh1 = pk2(w1.z, w1.w);
#pragma unroll
            for (int j = 0; j < 4; j++) {
                float xv = xsh[w][j][k];
                unsigned long long x2 = pk2(xv, xv);
                fma2(acc[j][0], x2, wl0);
                fma2(acc[j][1], x2, wh0);
                fma2(acc[j][2], x2, wl1);
                fma2(acc[j][3], x2, wh1);
            }
        }
        __syncthreads();
    }
    float4 b0 = ((const float4*)b2)[lane];
    float4 b1v = ((const float4*)b2)[32 + lane];
#pragma unroll
    for (int j = 0; j < 4; j++) {
        int row = row0 + j;
        float4 a0 = ((const float4*)(g_agg2 + row * 2 * HD))[lane];
        float4 a1 = ((const float4*)(g_agg2 + row * 2 * HD))[32 + lane];
        float m0, m1, m2, m3, v0, v1, v2, v3;
        upk2(acc[j][0], m0, m1);
        upk2(acc[j][1], m2, m3);
        upk2(acc[j][2], v0, v1);
        upk2(acc[j][3], v2, v3);
        m0 += a0.x + b0.x; m1 += a0.y + b0.y; m2 += a0.z + b0.z; m3 += a0.w + b0.w;
        v0 += a1.x + b1v.x; v1 += a1.y + b1v.y; v2 += a1.z + b1v.z; v3 += a1.w + b1v.w;
        float4 ev = ((const float4*)(eps + row * HD))[lane];
        float z0 = m0 + sqrtf(softplus_f(v0) + 1e-8f) * ev.x;
        float z1 = m1 + sqrtf(softplus_f(v1) + 1e-8f) * ev.y;
        float z2 = m2 + sqrtf(softplus_f(v2) + 1e-8f) * ev.z;
        float z3 = m3 + sqrtf(softplus_f(v3) + 1e-8f) * ev.w;
        ((float4*)(g_z + row * HD))[lane] = make_float4(z0, z1, z2, z3);
        // split to bf16 hi/lo for the tensor-core decoder
        __nv_bfloat16 h0b = __float2bfloat16(z0), h1b = __float2bfloat16(z1);
        __nv_bfloat16 h2b = __float2bfloat16(z2), h3b = __float2bfloat16(z3);
        __nv_bfloat16 l0b = __float2bfloat16(z0 - __bfloat162float(h0b));
        __nv_bfloat16 l1b = __float2bfloat16(z1 - __bfloat162float(h1b));
        __nv_bfloat16 l2b = __float2bfloat16(z2 - __bfloat162float(h2b));
        __nv_bfloat16 l3b = __float2bfloat16(z3 - __bfloat162float(h3b));
        __nv_bfloat162* zh = (__nv_bfloat162*)(g_zhi + row * HD);
        __nv_bfloat162* zl = (__nv_bfloat162*)(g_zlo + row * HD);
        zh[lane * 2]     = __nv_bfloat162(h0b, h1b);
        zh[lane * 2 + 1] = __nv_bfloat162(h2b, h3b);
        zl[lane * 2]     = __nv_bfloat162(l0b, l1b);
        zl[lane * 2 + 1] = __nv_bfloat162(l2b, l3b);
    }
}

// ---------------- 6) hr = z[head_ids] * w_rel[rel_ids], split to bf16 hi/lo ----------------
__global__ __launch_bounds__(256) void hr_kernel(const int* __restrict__ head_ids,
                                                 const int* __restrict__ rel_ids,
                                                 const float* __restrict__ w_rel) {
    int idx = blockIdx.x * blockDim.x + threadIdx.x;  // 0 .. 2048*128-1
    int b = idx >> 7, c = idx & 127;
    float v = g_z[head_ids[b] * HD + c] * w_rel[rel_ids[b] * HD + c];
    __nv_bfloat16 hi = __float2bfloat16(v);
    g_hrhi[idx] = hi;
    g_hrlo[idx] = __float2bfloat16(v - __bfloat162float(hi));
}

// ---------------- 7) decoder via mma.sync bf16 (split-bf16, 3 passes fused) -------------
// Per CTA: M=128 hr rows x N=128 z rows, K=128 resident in smem.
// 4 smem tiles (A hi/lo, B hi/lo), rows padded to 272B for conflict-free ldmatrix.
// 8 warps, each computes 64x32 (warp grid 2Mx4N); acc += Ahi*Bhi + Ahi*Blo + Alo*Bhi.
#define TROW 272
#define TILE_SB (128 * TROW)              // 34816 B per tile
#define DEC_SMEM (4 * TILE_SB)            // 139264 B

__global__ __launch_bounds__(256) void decoder_mma_kernel(float* __restrict__ out) {
    extern __shared__ char smem[];
    char* sAhi = smem;
    char* sAlo = smem + TILE_SB;
    char* sBhi = smem + 2 * TILE_SB;
    char* sBlo = smem + 3 * TILE_SB;
    int tid = threadIdx.x;
    int wid = tid >> 5, lane = tid & 31;
    int col0 = blockIdx.x * 128;   // N tile (z rows), 157 tiles, last partial
    int row0 = blockIdx.y * 128;   // M tile (hr rows), exact

    // ---- load 4 tiles: 128 rows x 256B each, padded stride ----
    {
        const __nv_bfloat16* srcs[4] = {g_hrhi, g_hrlo, g_zhi, g_zlo};
        char* dsts[4] = {sAhi, sAlo, sBhi, sBlo};
#pragma unroll
        for (int t = 0; t < 4; t++) {
            bool isB = (t >= 2);
            const __nv_bfloat16* src = srcs[t];
            char* dst = dsts[t];
#pragma unroll
            for (int it = 0; it < 8; it++) {
                int idx = tid + it * 256;       // 0..2047
                int r = idx >> 4, q = idx & 15; // row, 16B chunk
                uint4 v = make_uint4(0u, 0u, 0u, 0u);
                int grow = (isB ? col0 : row0) + r;
                if (!isB || grow < NN)
                    v = *(const uint4*)(src + grow * HD + q * 8);
                *(uint4*)(dst + r * TROW + q * 16) = v;
            }
        }
    }
    __syncthreads();

    // ---- warp tile: wr in {0,1} (64 M-rows), wc in {0..3} (32 N-cols) ----
    int wr = wid & 1, wc = wid >> 1;
    float acc[4][4][4];
#pragma unroll
    for (int mi = 0; mi < 4; mi++)
#pragma unroll
        for (int ni = 0; ni < 4; ni++)
#pragma unroll
            for (int x = 0; x < 4; x++) acc[mi][ni][x] = 0.f;

    // per-lane ldmatrix base addresses
    int aRow = wr * 64 + (lane & 7) + ((lane >> 3) & 1) * 8;
    int aKoff = ((lane >> 4) & 1) * 16;
    uint32_t aBaseHi = smem_to_u32(sAhi) + aRow * TROW + aKoff;
    uint32_t aBaseLo = smem_to_u32(sAlo) + aRow * TROW + aKoff;
    int bRow = wc * 32 + (lane & 7);
    int bKoff = ((lane >> 3) & 1) * 16;
    uint32_t bBaseHi = smem_to_u32(sBhi) + bRow * TROW + bKoff;
    uint32_t bBaseLo = smem_to_u32(sBlo) + bRow * TROW + bKoff;

#pragma unroll 1
    for (int ks = 0; ks < 8; ks++) {
        int ko = ks * 32;   // 16 bf16 = 32 bytes per k-step
        uint32_t ah[4][4], al[4][4], bh[4][2], bl[4][2];
#pragma unroll
        for (int mi = 0; mi < 4; mi++) {
            ldm_x4(ah[mi][0], ah[mi][1], ah[mi][2], ah[mi][3], aBaseHi + mi * 16 * TROW + ko);
            ldm_x4(al[mi][0], al[mi][1], al[mi][2], al[mi][3], aBaseLo + mi * 16 * TROW + ko);
        }
#pragma unroll
        for (int ni = 0; ni < 4; ni++) {
            ldm_x2(bh[ni][0], bh[ni][1], bBaseHi + ni * 8 * TROW + ko);
            ldm_x2(bl[ni][0], bl[ni][1], bBaseLo + ni * 8 * TROW + ko);
        }
#pragma unroll
        for (int mi = 0; mi < 4; mi++)
#pragma unroll
            for (int ni = 0; ni < 4; ni++) {
                mma_bf16(acc[mi][ni], ah[mi][0], ah[mi][1], ah[mi][2], ah[mi][3],
                         bh[ni][0], bh[ni][1]);
                mma_bf16(acc[mi][ni], ah[mi][0], ah[mi][1], ah[mi][2], ah[mi][3],
                         bl[ni][0], bl[ni][1]);
                mma_bf16(acc[mi][ni], al[mi][0], al[mi][1], al[mi][2], al[mi][3],
                         bh[ni][0], bh[ni][1]);
            }
    }

    // ---- store: lane l owns (m = l>>2 [+8], n = (l&3)*2 [,+1]) per atom ----
#pragma unroll
    for (int mi = 0; mi < 4; mi++) {
        int rgA = row0 + wr * 64 + mi * 16 + (lane >> 2);
        float* orow0 = out + (size_t)rgA * NN;
        float* orow1 = out + (size_t)(rgA + 8) * NN;
#pragma unroll
        for (int ni = 0; ni < 4; ni++) {
            int cg = col0 + wc * 32 + ni * 8 + (lane & 3) * 2;
            if (cg < NN) {   // NN even, (cg, cg+1) valid together
                *(float2*)(orow0 + cg) = make_float2(acc[mi][ni][0], acc[mi][ni][1]);
                *(float2*)(orow1 + cg) = make_float2(acc[mi][ni][2], acc[mi][ni][3]);
            }
        }
    }
}

// ---------------- launch ----------------
extern "C" void kernel_launch(void* const* d_in, const int* in_sizes, int n_in,
                              void* d_out, int out_size) {
    const int*   h        = (const int*)d_in[0];
    const int*   src      = (const int*)d_in[1];
    const int*   dst      = (const int*)d_in[2];
    const int*   etypes   = (const int*)d_in[3];
    const float* norm     = (const float*)d_in[4];
    const int*   head_ids = (const int*)d_in[5];
    const int*   rel_ids  = (const int*)d_in[6];
    const float* embed    = (const float*)d_in[7];
    const float* W1       = (const float*)d_in[8];
    const float* lw1      = (const float*)d_in[9];
    const float* b1       = (const float*)d_in[10];
    const float* W2       = (const float*)d_in[11];
    const float* lw2      = (const float*)d_in[12];
    const float* b2       = (const float*)d_in[13];
    const float* w_rel    = (const float*)d_in[14];
    const float* eps      = (const float*)d_in[15];
    float* out = (float*)d_out;

    cudaFuncSetAttribute(decoder_mma_kernel,
                         cudaFuncAttributeMaxDynamicSharedMemorySize, DEC_SMEM);

    init_kernel<<<(NN * 2 * HD) / 256, 256>>>(h, embed);
    hist_kernel<<<EE / 1024, 256>>>(etypes);
    scan_kernel<<<1, 128>>>();
    scatter_kernel<<<EE / 1024, 256>>>(src, dst, etypes, norm);
    edge1_kernel<<<EE / (EPW * 8), 256>>>(W1);
    selfloop1_kernel<<<NN / 32, 256>>>(lw1, b1);
    edge2_kernel<<<EE / (EPW * 8), 256>>>(W2);
    selfloop2_kernel<<<NN / 32, 256>>>(lw2, b2, eps);
    hr_kernel<<<(2048 * HD) / 256, 256>>>(head_ids, rel_ids, w_rel);
    dim3 dgrid((NN + 127) / 128, 2048 / 128);
    decoder_mma_kernel<<<dgrid, 256, DEC_SMEM>>>(out);
}

// round 7
// speedup vs baseline: 1.8190x; 1.0711x over previous
#include <cuda_runtime.h>
#include <cuda_bf16.h>
#include <cstdint>

#define NN 20000
#define EE 256000
#define HD 128
#define NRR 100
#define EPW 16   // edges per warp in sorted edge kernels

// ---------------- scratch (static device globals; no allocation) ----------------
__device__ float g_x0[NN * HD];        // embed[h]
__device__ float g_agg1[NN * HD];      // layer1 aggregation
__device__ float g_out1[NN * HD];      // layer1 output (relu)
__device__ float g_agg2[NN * 2 * HD];  // layer2 aggregation
__device__ float g_z[NN * HD];         // sampled latent (fp32, for hr gather)
__device__ __nv_bfloat16 g_zhi[NN * HD];
__device__ __nv_bfloat16 g_zlo[NN * HD];
__device__ __nv_bfloat16 g_hrhi[2048 * HD];
__device__ __nv_bfloat16 g_hrlo[2048 * HD];
__device__ int   g_hist[NRR + 1];      // relation histogram / offsets
__device__ int   g_cursor[NRR];        // scatter cursors
__device__ int4  g_recs[EE];           // sorted edge records {src, dst, rel, norm}

// ---------------- helpers ----------------
__device__ __forceinline__ unsigned long long pk2(float x, float y) {
    unsigned long long r;
    asm("mov.b64 %0, {%1, %2};" : "=l"(r) : "f"(x), "f"(y));
    return r;
}
__device__ __forceinline__ void upk2(unsigned long long p, float& x, float& y) {
    asm("mov.b64 {%0, %1}, %2;" : "=f"(x), "=f"(y) : "l"(p));
}
__device__ __forceinline__ void fma2(unsigned long long& d, unsigned long long a, unsigned long long b) {
    asm("fma.rn.f32x2 %0, %1, %2, %0;" : "+l"(d) : "l"(a), "l"(b));
}
__device__ __forceinline__ void red_add_v4(float* addr, float a, float b, float c, float d) {
    asm volatile("red.global.add.v4.f32 [%0], {%1, %2, %3, %4};"
                 :: "l"(addr), "f"(a), "f"(b), "f"(c), "f"(d) : "memory");
}
__device__ __forceinline__ float softplus_f(float x) {
    return fmaxf(x, 0.f) + log1pf(expf(-fabsf(x)));
}
__device__ __forceinline__ uint32_t smem_to_u32(const void* p) {
    uint32_t a;
    asm("{ .reg .u64 t; cvta.to.shared.u64 t, %1; cvt.u32.u64 %0, t; }" : "=r"(a) : "l"(p));
    return a;
}
__device__ __forceinline__ void ldm_x4(uint32_t& r0, uint32_t& r1, uint32_t& r2, uint32_t& r3,
                                       uint32_t addr) {
    asm volatile("ldmatrix.sync.aligned.m8n8.x4.shared.b16 {%0,%1,%2,%3}, [%4];"
                 : "=r"(r0), "=r"(r1), "=r"(r2), "=r"(r3) : "r"(addr));
}
__device__ __forceinline__ void ldm_x2(uint32_t& r0, uint32_t& r1, uint32_t addr) {
    asm volatile("ldmatrix.sync.aligned.m8n8.x2.shared.b16 {%0,%1}, [%2];"
                 : "=r"(r0), "=r"(r1) : "r"(addr));
}
__device__ __forceinline__ void mma_bf16(float* c, uint32_t a0, uint32_t a1, uint32_t a2,
                                         uint32_t a3, uint32_t b0, uint32_t b1) {
    asm volatile(
        "mma.sync.aligned.m16n8k16.row.col.f32.bf16.bf16.f32 "
        "{%0,%1,%2,%3}, {%4,%5,%6,%7}, {%8,%9}, {%0,%1,%2,%3};"
        : "+f"(c[0]), "+f"(c[1]), "+f"(c[2]), "+f"(c[3])
        : "r"(a0), "r"(a1), "r"(a2), "r"(a3), "r"(b0), "r"(b1));
}

// ---------------- 1) gather x0 = embed[h], zero agg buffers + sort state ----------------
__global__ __launch_bounds__(256) void init_kernel(const int* __restrict__ h,
                                                   const float* __restrict__ embed) {
    int idx = blockIdx.x * blockDim.x + threadIdx.x;  // 0 .. N*256-1
    if (idx < NN * HD) {
        g_x0[idx] = embed[h[idx >> 7] * HD + (idx & 127)];
        g_agg1[idx] = 0.f;
    }
    g_agg2[idx] = 0.f;
    if (idx <= NRR) g_hist[idx] = 0;
}

// ---------------- sort pass A: relation histogram (1024 edges/block) ----------------
__global__ __launch_bounds__(256) void hist_kernel(const int* __restrict__ et) {
    __shared__ int sh[NRR];
    int tid = threadIdx.x;
    if (tid < NRR) sh[tid] = 0;
    __syncthreads();
    int e0 = blockIdx.x * 1024 + tid;
#pragma unroll
    for (int j = 0; j < 4; j++) atomicAdd(&sh[et[e0 + j * 256]], 1);
    __syncthreads();
    if (tid < NRR && sh[tid]) atomicAdd(&g_hist[tid + 1], sh[tid]);
}

// ---------------- sort pass B: parallel inclusive scan of 101 values ----------------
__global__ __launch_bounds__(128) void scan_kernel() {
    __shared__ int s[128];
    int tid = threadIdx.x;
    s[tid] = (tid <= NRR) ? g_hist[tid] : 0;
    __syncthreads();
#pragma unroll
    for (int d = 1; d < 128; d <<= 1) {
        int v = (tid >= d) ? s[tid - d] : 0;
        __syncthreads();
        s[tid] += v;
        __syncthreads();
    }
    if (tid <= NRR) g_hist[tid] = s[tid];
    if (tid < NRR) g_cursor[tid] = s[tid];
}

// ---------------- sort pass C: block-aggregated scatter (1024 edges/block) ----------------
__global__ __launch_bounds__(256) void scatter_kernel(const int* __restrict__ src,
                                                      const int* __restrict__ dst,
                                                      const int* __restrict__ et,
                                                      const float* __restrict__ norm) {
    __shared__ int cnt[NRR];
    __shared__ int base[NRR];
    int tid = threadIdx.x;
    if (tid < NRR) cnt[tid] = 0;
    __syncthreads();
    int e0 = blockIdx.x * 1024 + tid;
    int r[4], s[4], d[4], nm[4];
#pragma unroll
    for (int j = 0; j < 4; j++) {
        int e = e0 + j * 256;
        r[j] = et[e]; s[j] = src[e]; d[j] = dst[e]; nm[j] = __float_as_int(norm[e]);
        atomicAdd(&cnt[r[j]], 1);
    }
    __syncthreads();
    if (tid < NRR) {
        int c = cnt[tid];
        base[tid] = c ? atomicAdd(&g_cursor[tid], c) : 0;
        cnt[tid] = 0;
    }
    __syncthreads();
#pragma unroll
    for (int j = 0; j < 4; j++) {
        int pos = base[r[j]] + atomicAdd(&cnt[r[j]], 1);
        g_recs[pos] = make_int4(s[j], d[j], r[j], nm[j]);
    }
}

// ---------------- 2) layer1 edge messages: warp walks EPW sorted edges ----------------
__global__ __launch_bounds__(256) void edge1_kernel(const float* __restrict__ W1) {
    int warp = (blockIdx.x * 256 + threadIdx.x) >> 5;
    int lane = threadIdx.x & 31;
    int e0 = warp * EPW;
    int cur = -1;
    float4 wa, wb;
    int4 rec = __ldg(&g_recs[e0]);
#pragma unroll 1
    for (int e = 0; e < EPW; e++) {
        int4 nrec = (e + 1 < EPW) ? __ldg(&g_recs[e0 + e + 1]) : rec;
        int s = rec.x, d = rec.y, r = rec.z;
        float nrm = __int_as_float(rec.w);
        float4 xv = ((const float4*)(g_x0 + s * HD))[lane];
        if (r != cur) {                        // warp-uniform branch, rare
            const float4* w4 = (const float4*)(W1 + r * 256 + lane * 8);
            wa = __ldg(w4); wb = __ldg(w4 + 1);
            cur = r;
        }
        float o0 = (xv.x * wa.x + xv.y * wa.z) * nrm;
        float o1 = (xv.x * wa.y + xv.y * wa.w) * nrm;
        float o2 = (xv.z * wb.x + xv.w * wb.z) * nrm;
        float o3 = (xv.z * wb.y + xv.w * wb.w) * nrm;
        red_add_v4(g_agg1 + d * HD + lane * 4, o0, o1, o2, o3);
        rec = nrec;
    }
}

// ---------------- 3) self-loop layer1: out1 = relu(agg1 + x0 @ lw1 + b1) ----------------
__global__ __launch_bounds__(256) void selfloop1_kernel(const float* __restrict__ lw1,
                                                        const float* __restrict__ b1) {
    __shared__ float4 ws4[32][32];
    __shared__ float xsh[8][4][33];
    int tid = threadIdx.x;
    int w = tid >> 5, lane = tid & 31;
    int row0 = blockIdx.x * 32 + w * 4;
    unsigned long long acc[4][2];
#pragma unroll
    for (int j = 0; j < 4; j++) { acc[j][0] = 0ULL; acc[j][1] = 0ULL; }
    const float4* lw4 = (const float4*)lw1;
    for (int kc = 0; kc < 4; kc++) {
#pragma unroll
        for (int it = 0; it < 4; it++) {
            int idx = tid + it * 256;
            int k = idx >> 5, c = idx & 31;
            ws4[k][c] = lw4[(kc * 32 + k) * 32 + c];
        }
#pragma unroll
        for (int j = 0; j < 4; j++)
            xsh[w][j][lane] = g_x0[(row0 + j) * HD + kc * 32 + lane];
        __syncthreads();
#pragma unroll
        for (int k = 0; k < 32; k++) {
            float4 wv = ws4[k][lane];
            unsigned long long wlo = pk2(wv.x, wv.y), whi = pk2(wv.z, wv.w);
#pragma unroll
            for (int j = 0; j < 4; j++) {
                float xv = xsh[w][j][k];
                unsigned long long x2 = pk2(xv, xv);
                fma2(acc[j][0], x2, wlo);
                fma2(acc[j][1], x2, whi);
            }
        }
        __syncthreads();
    }
    float4 bv = ((const float4*)b1)[lane];
#pragma unroll
    for (int j = 0; j < 4; j++) {
        int row = row0 + j;
        float4 av = ((const float4*)(g_agg1 + row * HD))[lane];
        float o0, o1, o2, o3;
        upk2(acc[j][0], o0, o1);
        upk2(acc[j][1], o2, o3);
        o0 = fmaxf(o0 + av.x + bv.x, 0.f);
        o1 = fmaxf(o1 + av.y + bv.y, 0.f);
        o2 = fmaxf(o2 + av.z + bv.z, 0.f);
        o3 = fmaxf(o3 + av.w + bv.w, 0.f);
        ((float4*)(g_out1 + row * HD))[lane] = make_float4(o0, o1, o2, o3);
    }
}

// ---------------- 4) layer2 edge messages: warp walks EPW sorted edges ----------------
__global__ __launch_bounds__(256) void edge2_kernel(const float* __restrict__ W2) {
    int warp = (blockIdx.x * 256 + threadIdx.x) >> 5;
    int lane = threadIdx.x & 31;
    int e0 = warp * EPW;
    int cur = -1;
    float4 wA, wB, wC, wD;
    int4 rec = __ldg(&g_recs[e0]);
#pragma unroll 1
    for (int e = 0; e < EPW; e++) {
        int4 nrec = (e + 1 < EPW) ? __ldg(&g_recs[e0 + e + 1]) : rec;
        int s = rec.x, d = rec.y, r = rec.z;
        float nrm = __int_as_float(rec.w);
        float4 xv = ((const float4*)(g_out1 + s * HD))[lane];
        if (r != cur) {
            const float4* w4 = (const float4*)(W2 + r * 512 + lane * 16);
            wA = __ldg(w4);
            wB = __ldg(w4 + 1);
            wC = __ldg(w4 + 2);
            wD = __ldg(w4 + 3);
            cur = r;
        }
        float l0 = (xv.x * wA.x + xv.y * wB.x) * nrm;
        float l1 = (xv.x * wA.y + xv.y * wB.y) * nrm;
        float l2 = (xv.x * wA.z + xv.y * wB.z) * nrm;
        float l3 = (xv.x * wA.w + xv.y * wB.w) * nrm;
        float h0 = (xv.z * wC.x + xv.w * wD.x) * nrm;
        float h1 = (xv.z * wC.y + xv.w * wD.y) * nrm;
        float h2 = (xv.z * wC.z + xv.w * wD.z) * nrm;
        float h3 = (xv.z * wC.w + xv.w * wD.w) * nrm;
        float* base = g_agg2 + d * 2 * HD + lane * 8;
        red_add_v4(base, l0, l1, l2, l3);
        red_add_v4(base + 4, h0, h1, h2, h3);
        rec = nrec;
    }
}

// ---------------- 5) self-loop layer2 + gaussian sample + bf16 split, fused ----------------
__global__ __launch_bounds__(256) void selfloop2_kernel(const float* __restrict__ lw2,
                                                        const float* __restrict__ b2,
                                                        const float* __restrict__ eps) {
    __shared__ float4 ws4[32][64];
    __shared__ float xsh[8][4][33];
    int tid = threadIdx.x;
    int w = tid >> 5, lane = tid & 31;
    int row0 = blockIdx.x * 32 + w * 4;
    unsigned long long acc[4][4];
#pragma unroll
    for (int j = 0; j < 4; j++)
#pragma unroll
        for (int g = 0; g < 4; g++) acc[j][g] = 0ULL;
    const float4* lw4 = (const float4*)lw2;
    for (int kc = 0; kc < 4; kc++) {
#pragma unroll
        for (int it = 0; it < 8; it++) {
            int idx = tid + it * 256;
            int k = idx >> 6, c = idx & 63;
            ws4[k][c] = lw4[(kc * 32 + k) * 64 + c];
        }
#pragma unroll
        for (int j = 0; j < 4; j++)
            xsh[w][j][lane] = g_out1[(row0 + j) * HD + kc * 32 + lane];
        __syncthreads();
#pragma unroll
        for (int k = 0; k < 32; k++) {
            float4 w0 = ws4[k][lane];
            float4 w1 = ws4[k][32 + lane];
            unsigned long long wl0 = pk2(w0.x, w0.y), wh0 = pk2(w0.z, w0.w);
            unsigned long long wl1 = pk2(w1.x, w1.y), wh1 = pk2(w1.z, w1.w);
#pragma unroll
            for (int j = 0; j < 4; j++) {
                float xv = xsh[w][j][k];
                unsigned long long x2 = pk2(xv, xv);
                fma2(acc[j][0], x2, wl0);
                fma2(acc[j][1], x2, wh0);
                fma2(acc[j][2], x2, wl1);
                fma2(acc[j][3], x2, wh1);
            }
        }
        __syncthreads();
    }
    float4 b0 = ((const float4*)b2)[lane];
    float4 b1v = ((const float4*)b2)[32 + lane];
#pragma unroll
    for (int j = 0; j < 4; j++) {
        int row = row0 + j;
        float4 a0 = ((const float4*)(g_agg2 + row * 2 * HD))[lane];
        float4 a1 = ((const float4*)(g_agg2 + row * 2 * HD))[32 + lane];
        float m0, m1, m2, m3, v0, v1, v2, v3;
        upk2(acc[j][0], m0, m1);
        upk2(acc[j][1], m2, m3);
        upk2(acc[j][2], v0, v1);
        upk2(acc[j][3], v2, v3);
        m0 += a0.x + b0.x; m1 += a0.y + b0.y; m2 += a0.z + b0.z; m3 += a0.w + b0.w;
        v0 += a1.x + b1v.x; v1 += a1.y + b1v.y; v2 += a1.z + b1v.z; v3 += a1.w + b1v.w;
        float4 ev = ((const float4*)(eps + row * HD))[lane];
        float z0 = m0 + sqrtf(softplus_f(v0) + 1e-8f) * ev.x;
        float z1 = m1 + sqrtf(softplus_f(v1) + 1e-8f) * ev.y;
        float z2 = m2 + sqrtf(softplus_f(v2) + 1e-8f) * ev.z;
        float z3 = m3 + sqrtf(softplus_f(v3) + 1e-8f) * ev.w;
        ((float4*)(g_z + row * HD))[lane] = make_float4(z0, z1, z2, z3);
        // split to bf16 hi/lo for the tensor-core decoder
        __nv_bfloat16 h0b = __float2bfloat16(z0), h1b = __float2bfloat16(z1);
        __nv_bfloat16 h2b = __float2bfloat16(z2), h3b = __float2bfloat16(z3);
        __nv_bfloat16 l0b = __float2bfloat16(z0 - __bfloat162float(h0b));
        __nv_bfloat16 l1b = __float2bfloat16(z1 - __bfloat162float(h1b));
        __nv_bfloat16 l2b = __float2bfloat16(z2 - __bfloat162float(h2b));
        __nv_bfloat16 l3b = __float2bfloat16(z3 - __bfloat162float(h3b));
        __nv_bfloat162* zh = (__nv_bfloat162*)(g_zhi + row * HD);
        __nv_bfloat162* zl = (__nv_bfloat162*)(g_zlo + row * HD);
        zh[lane * 2]     = __nv_bfloat162(h0b, h1b);
        zh[lane * 2 + 1] = __nv_bfloat162(h2b, h3b);
        zl[lane * 2]     = __nv_bfloat162(l0b, l1b);
        zl[lane * 2 + 1] = __nv_bfloat162(l2b, l3b);
    }
}

// ---------------- 6) hr = z[head_ids] * w_rel[rel_ids], split to bf16 hi/lo ----------------
__global__ __launch_bounds__(256) void hr_kernel(const int* __restrict__ head_ids,
                                                 const int* __restrict__ rel_ids,
                                                 const float* __restrict__ w_rel) {
    int idx = blockIdx.x * blockDim.x + threadIdx.x;  // 0 .. 2048*128-1
    int b = idx >> 7, c = idx & 127;
    float v = g_z[head_ids[b] * HD + c] * w_rel[rel_ids[b] * HD + c];
    __nv_bfloat16 hi = __float2bfloat16(v);
    g_hrhi[idx] = hi;
    g_hrlo[idx] = __float2bfloat16(v - __bfloat162float(hi));
}

// ---------------- 7) decoder via mma.sync bf16 (split-bf16, K-chunked, 2 CTAs/SM) -------
// Per CTA: 128x128 output tile; K=128 processed in 2 chunks of 64 so the 4 smem tiles
// (A hi/lo, B hi/lo) shrink to 18KB each -> 72KB/CTA -> 2 CTAs/SM overlap load & MMA.
// Row stride 144B keeps ldmatrix conflict-free (rows spread over all 8 bank groups).
#define TROW 144
#define TILE_SB (128 * TROW)              // 18432 B per tile
#define DEC_SMEM (4 * TILE_SB)            // 73728 B

__global__ __launch_bounds__(256, 2) void decoder_mma_kernel(float* __restrict__ out) {
    extern __shared__ char smem[];
    char* sAhi = smem;
    char* sAlo = smem + TILE_SB;
    char* sBhi = smem + 2 * TILE_SB;
    char* sBlo = smem + 3 * TILE_SB;
    int tid = threadIdx.x;
    int wid = tid >> 5, lane = tid & 31;
    int col0 = blockIdx.x * 128;   // N tile (z rows), 157 tiles, last partial
    int row0 = blockIdx.y * 128;   // M tile (hr rows), exact

    int wr = wid & 1, wc = wid >> 1;
    float acc[4][4][4];
#pragma unroll
    for (int mi = 0; mi < 4; mi++)
#pragma unroll
        for (int ni = 0; ni < 4; ni++)
#pragma unroll
            for (int x = 0; x < 4; x++) acc[mi][ni][x] = 0.f;

    // per-lane ldmatrix base addresses
    int aRow = wr * 64 + (lane & 7) + ((lane >> 3) & 1) * 8;
    int aKoff = ((lane >> 4) & 1) * 16;
    uint32_t aBaseHi = smem_to_u32(sAhi) + aRow * TROW + aKoff;
    uint32_t aBaseLo = smem_to_u32(sAlo) + aRow * TROW + aKoff;
    int bRow = wc * 32 + (lane & 7);
    int bKoff = ((lane >> 3) & 1) * 16;
    uint32_t bBaseHi = smem_to_u32(sBhi) + bRow * TROW + bKoff;
    uint32_t bBaseLo = smem_to_u32(sBlo) + bRow * TROW + bKoff;

    const __nv_bfloat16* srcs[4] = {g_hrhi, g_hrlo, g_zhi, g_zlo};
    char* dsts[4] = {sAhi, sAlo, sBhi, sBlo};

#pragma unroll 1
    for (int kc = 0; kc < 2; kc++) {
        // ---- load 4 tiles of this K-chunk: 128 rows x 128B each ----
#pragma unroll
        for (int t = 0; t < 4; t++) {
            bool isB = (t >= 2);
            const __nv_bfloat16* src = srcs[t];
            char* dst = dsts[t];
#pragma unroll
            for (int it = 0; it < 4; it++) {
                int idx = tid + it * 256;       // 0..1023
                int r = idx >> 3, q = idx & 7;  // row, 16B chunk
                uint4 v = make_uint4(0u, 0u, 0u, 0u);
                int grow = (isB ? col0 : row0) + r;
                if (!isB || grow < NN)
                    v = *(const uint4*)(src + grow * HD + kc * 64 + q * 8);
                *(uint4*)(dst + r * TROW + q * 16) = v;
            }
        }
        __syncthreads();

        // ---- 4 k16-steps over this chunk ----
#pragma unroll
        for (int ks = 0; ks < 4; ks++) {
            int ko = ks * 32;   // 16 bf16 = 32 bytes per k-step
            uint32_t bh[4][2], bl[4][2];
#pragma unroll
            for (int ni = 0; ni < 4; ni++) {
                ldm_x2(bh[ni][0], bh[ni][1], bBaseHi + ni * 8 * TROW + ko);
                ldm_x2(bl[ni][0], bl[ni][1], bBaseLo + ni * 8 * TROW + ko);
            }
#pragma unroll
            for (int mi = 0; mi < 4; mi++) {
                uint32_t ah0, ah1, ah2, ah3, al0, al1, al2, al3;
                ldm_x4(ah0, ah1, ah2, ah3, aBaseHi + mi * 16 * TROW + ko);
                ldm_x4(al0, al1, al2, al3, aBaseLo + mi * 16 * TROW + ko);
#pragma unroll
                for (int ni = 0; ni < 4; ni++) {
                    mma_bf16(acc[mi][ni], ah0, ah1, ah2, ah3, bh[ni][0], bh[ni][1]);
                    mma_bf16(acc[mi][ni], ah0, ah1, ah2, ah3, bl[ni][0], bl[ni][1]);
                    mma_bf16(acc[mi][ni], al0, al1, al2, al3, bh[ni][0], bh[ni][1]);
                }
            }
        }
        __syncthreads();
    }

    // ---- store: lane l owns (m = l>>2 [+8], n = (l&3)*2 [,+1]) per atom ----
#pragma unroll
    for (int mi = 0; mi < 4; mi++) {
        int rgA = row0 + wr * 64 + mi * 16 + (lane >> 2);
        float* orow0 = out + (size_t)rgA * NN;
        float* orow1 = out + (size_t)(rgA + 8) * NN;
#pragma unroll
        for (int ni = 0; ni < 4; ni++) {
            int cg = col0 + wc * 32 + ni * 8 + (lane & 3) * 2;
            if (cg < NN) {   // NN even, (cg, cg+1) valid together
                *(float2*)(orow0 + cg) = make_float2(acc[mi][ni][0], acc[mi][ni][1]);
                *(float2*)(orow1 + cg) = make_float2(acc[mi][ni][2], acc[mi][ni][3]);
            }
        }
    }
}

// ---------------- launch ----------------
extern "C" void kernel_launch(void* const* d_in, const int* in_sizes, int n_in,
                              void* d_out, int out_size) {
    const int*   h        = (const int*)d_in[0];
    const int*   src      = (const int*)d_in[1];
    const int*   dst      = (const int*)d_in[2];
    const int*   etypes   = (const int*)d_in[3];
    const float* norm     = (const float*)d_in[4];
    const int*   head_ids = (const int*)d_in[5];
    const int*   rel_ids  = (const int*)d_in[6];
    const float* embed    = (const float*)d_in[7];
    const float* W1       = (const float*)d_in[8];
    const float* lw1      = (const float*)d_in[9];
    const float* b1       = (const float*)d_in[10];
    const float* W2       = (const float*)d_in[11];
    const float* lw2      = (const float*)d_in[12];
    const float* b2       = (const float*)d_in[13];
    const float* w_rel    = (const float*)d_in[14];
    const float* eps      = (const float*)d_in[15];
    float* out = (float*)d_out;

    cudaFuncSetAttribute(decoder_mma_kernel,
                         cudaFuncAttributeMaxDynamicSharedMemorySize, DEC_SMEM);

    init_kernel<<<(NN * 2 * HD) / 256, 256>>>(h, embed);
    hist_kernel<<<EE / 1024, 256>>>(etypes);
    scan_kernel<<<1, 128>>>();
    scatter_kernel<<<EE / 1024, 256>>>(src, dst, etypes, norm);
    edge1_kernel<<<EE / (EPW * 8), 256>>>(W1);
    selfloop1_kernel<<<NN / 32, 256>>>(lw1, b1);
    edge2_kernel<<<EE / (EPW * 8), 256>>>(W2);
    selfloop2_kernel<<<NN / 32, 256>>>(lw2, b2, eps);
    hr_kernel<<<(2048 * HD) / 256, 256>>>(head_ids, rel_ids, w_rel);
    dim3 dgrid((NN + 127) / 128, 2048 / 128);
    decoder_mma_kernel<<<dgrid, 256, DEC_SMEM>>>(out);
}

// round 8
// speedup vs baseline: 1.8216x; 1.0014x over previous
#include <cuda_runtime.h>
#include <cuda_bf16.h>
#include <cstdint>

#define NN 20000
#define EE 256000
#define HD 128
#define NRR 100
#define EPW 16   // edges per warp in sorted edge kernels

// ---------------- scratch (static device globals; no allocation) ----------------
__device__ float g_x0[NN * HD];        // embed[h]
__device__ float g_agg1[NN * HD];      // layer1 aggregation
__device__ float g_out1[NN * HD];      // layer1 output (relu)
__device__ float g_agg2[NN * 2 * HD];  // layer2 aggregation
__device__ float g_z[NN * HD];         // sampled latent (fp32, for hr gather)
__device__ __nv_bfloat16 g_zhi[NN * HD];
__device__ __nv_bfloat16 g_zlo[NN * HD];
__device__ __nv_bfloat16 g_hrhi[2048 * HD];
__device__ __nv_bfloat16 g_hrlo[2048 * HD];
__device__ int   g_hist[NRR + 1];      // relation histogram / offsets
__device__ int   g_cursor[NRR];        // scatter cursors
__device__ int4  g_recs[EE];           // sorted edge records {src, dst, rel, norm}

// ---------------- helpers ----------------
__device__ __forceinline__ unsigned long long pk2(float x, float y) {
    unsigned long long r;
    asm("mov.b64 %0, {%1, %2};" : "=l"(r) : "f"(x), "f"(y));
    return r;
}
__device__ __forceinline__ void upk2(unsigned long long p, float& x, float& y) {
    asm("mov.b64 {%0, %1}, %2;" : "=f"(x), "=f"(y) : "l"(p));
}
__device__ __forceinline__ void fma2(unsigned long long& d, unsigned long long a, unsigned long long b) {
    asm("fma.rn.f32x2 %0, %1, %2, %0;" : "+l"(d) : "l"(a), "l"(b));
}
// NOTE: no "memory" clobber — aggregates are only consumed by LATER KERNELS
// (device-wide fence at launch boundary), so the compiler may pipeline loads past it.
__device__ __forceinline__ void red_add_v4(float* addr, float a, float b, float c, float d) {
    asm volatile("red.global.add.v4.f32 [%0], {%1, %2, %3, %4};"
                 :: "l"(addr), "f"(a), "f"(b), "f"(c), "f"(d));
}
__device__ __forceinline__ float softplus_f(float x) {
    return fmaxf(x, 0.f) + log1pf(expf(-fabsf(x)));
}
__device__ __forceinline__ uint32_t smem_to_u32(const void* p) {
    uint32_t a;
    asm("{ .reg .u64 t; cvta.to.shared.u64 t, %1; cvt.u32.u64 %0, t; }" : "=r"(a) : "l"(p));
    return a;
}
__device__ __forceinline__ void ldm_x4(uint32_t& r0, uint32_t& r1, uint32_t& r2, uint32_t& r3,
                                       uint32_t addr) {
    asm volatile("ldmatrix.sync.aligned.m8n8.x4.shared.b16 {%0,%1,%2,%3}, [%4];"
                 : "=r"(r0), "=r"(r1), "=r"(r2), "=r"(r3) : "r"(addr));
}
__device__ __forceinline__ void ldm_x2(uint32_t& r0, uint32_t& r1, uint32_t addr) {
    asm volatile("ldmatrix.sync.aligned.m8n8.x2.shared.b16 {%0,%1}, [%2];"
                 : "=r"(r0), "=r"(r1) : "r"(addr));
}
__device__ __forceinline__ void mma_bf16(float* c, uint32_t a0, uint32_t a1, uint32_t a2,
                                         uint32_t a3, uint32_t b0, uint32_t b1) {
    asm volatile(
        "mma.sync.aligned.m16n8k16.row.col.f32.bf16.bf16.f32 "
        "{%0,%1,%2,%3}, {%4,%5,%6,%7}, {%8,%9}, {%0,%1,%2,%3};"
        : "+f"(c[0]), "+f"(c[1]), "+f"(c[2]), "+f"(c[3])
        : "r"(a0), "r"(a1), "r"(a2), "r"(a3), "r"(b0), "r"(b1));
}

// ---------------- 1) gather x0 = embed[h], zero agg buffers + sort state ----------------
__global__ __launch_bounds__(256) void init_kernel(const int* __restrict__ h,
                                                   const float* __restrict__ embed) {
    int idx = blockIdx.x * blockDim.x + threadIdx.x;  // 0 .. N*256-1
    if (idx < NN * HD) {
        g_x0[idx] = embed[h[idx >> 7] * HD + (idx & 127)];
        g_agg1[idx] = 0.f;
    }
    g_agg2[idx] = 0.f;
    if (idx <= NRR) g_hist[idx] = 0;
}

// ---------------- sort pass A: relation histogram (1024 edges/block) ----------------
__global__ __launch_bounds__(256) void hist_kernel(const int* __restrict__ et) {
    __shared__ int sh[NRR];
    int tid = threadIdx.x;
    if (tid < NRR) sh[tid] = 0;
    __syncthreads();
    int e0 = blockIdx.x * 1024 + tid;
#pragma unroll
    for (int j = 0; j < 4; j++) atomicAdd(&sh[et[e0 + j * 256]], 1);
    __syncthreads();
    if (tid < NRR && sh[tid]) atomicAdd(&g_hist[tid + 1], sh[tid]);
}

// ---------------- sort pass B: parallel inclusive scan of 101 values ----------------
__global__ __launch_bounds__(128) void scan_kernel() {
    __shared__ int s[128];
    int tid = threadIdx.x;
    s[tid] = (tid <= NRR) ? g_hist[tid] : 0;
    __syncthreads();
#pragma unroll
    for (int d = 1; d < 128; d <<= 1) {
        int v = (tid >= d) ? s[tid - d] : 0;
        __syncthreads();
        s[tid] += v;
        __syncthreads();
    }
    if (tid <= NRR) g_hist[tid] = s[tid];
    if (tid < NRR) g_cursor[tid] = s[tid];
}

// ---------------- sort pass C: block-aggregated scatter (1024 edges/block) ----------------
__global__ __launch_bounds__(256) void scatter_kernel(const int* __restrict__ src,
                                                      const int* __restrict__ dst,
                                                      const int* __restrict__ et,
                                                      const float* __restrict__ norm) {
    __shared__ int cnt[NRR];
    __shared__ int base[NRR];
    int tid = threadIdx.x;
    if (tid < NRR) cnt[tid] = 0;
    __syncthreads();
    int e0 = blockIdx.x * 1024 + tid;
    int r[4], s[4], d[4], nm[4];
#pragma unroll
    for (int j = 0; j < 4; j++) {
        int e = e0 + j * 256;
        r[j] = et[e]; s[j] = src[e]; d[j] = dst[e]; nm[j] = __float_as_int(norm[e]);
        atomicAdd(&cnt[r[j]], 1);
    }
    __syncthreads();
    if (tid < NRR) {
        int c = cnt[tid];
        base[tid] = c ? atomicAdd(&g_cursor[tid], c) : 0;
        cnt[tid] = 0;
    }
    __syncthreads();
#pragma unroll
    for (int j = 0; j < 4; j++) {
        int pos = base[r[j]] + atomicAdd(&cnt[r[j]], 1);
        g_recs[pos] = make_int4(s[j], d[j], r[j], nm[j]);
    }
}

// ---------------- 2) layer1 edge messages: warp walks EPW sorted edges, 2 at a time ------
// lane l handles blocks 2l,2l+1 (output cols 4l..4l+3); W cached in regs per relation run
__global__ __launch_bounds__(256) void edge1_kernel(const float* __restrict__ W1) {
    int warp = (blockIdx.x * 256 + threadIdx.x) >> 5;
    int lane = threadIdx.x & 31;
    int e0 = warp * EPW;
    int cur = -1;
    float4 wa, wb;
    int4 r0 = __ldg(&g_recs[e0]);
    int4 r1 = __ldg(&g_recs[e0 + 1]);
#pragma unroll 1
    for (int e = 0; e < EPW; e += 2) {
        int4 n0 = r0, n1 = r1;
        if (e + 2 < EPW) {
            n0 = __ldg(&g_recs[e0 + e + 2]);
            n1 = __ldg(&g_recs[e0 + e + 3]);
        }
        // both gathers issued before any reduction
        float4 xv0 = ((const float4*)(g_x0 + r0.x * HD))[lane];
        float4 xv1 = ((const float4*)(g_x0 + r1.x * HD))[lane];
        float nrm0 = __int_as_float(r0.w), nrm1 = __int_as_float(r1.w);
        if (r0.z != cur) {
            const float4* w4 = (const float4*)(W1 + r0.z * 256 + lane * 8);
            wa = __ldg(w4); wb = __ldg(w4 + 1);
            cur = r0.z;
        }
        float a0 = (xv0.x * wa.x + xv0.y * wa.z) * nrm0;
        float a1 = (xv0.x * wa.y + xv0.y * wa.w) * nrm0;
        float a2 = (xv0.z * wb.x + xv0.w * wb.z) * nrm0;
        float a3 = (xv0.z * wb.y + xv0.w * wb.w) * nrm0;
        red_add_v4(g_agg1 + r0.y * HD + lane * 4, a0, a1, a2, a3);
        if (r1.z != cur) {
            const float4* w4 = (const float4*)(W1 + r1.z * 256 + lane * 8);
            wa = __ldg(w4); wb = __ldg(w4 + 1);
            cur = r1.z;
        }
        float b0 = (xv1.x * wa.x + xv1.y * wa.z) * nrm1;
        float b1 = (xv1.x * wa.y + xv1.y * wa.w) * nrm1;
        float b2 = (xv1.z * wb.x + xv1.w * wb.z) * nrm1;
        float b3 = (xv1.z * wb.y + xv1.w * wb.w) * nrm1;
        red_add_v4(g_agg1 + r1.y * HD + lane * 4, b0, b1, b2, b3);
        r0 = n0; r1 = n1;
    }
}

// ---------------- 3) self-loop layer1: out1 = relu(agg1 + x0 @ lw1 + b1) ----------------
__global__ __launch_bounds__(256) void selfloop1_kernel(const float* __restrict__ lw1,
                                                        const float* __restrict__ b1) {
    __shared__ float4 ws4[32][32];
    __shared__ float xsh[8][4][33];
    int tid = threadIdx.x;
    int w = tid >> 5, lane = tid & 31;
    int row0 = blockIdx.x * 32 + w * 4;
    unsigned long long acc[4][2];
#pragma unroll
    for (int j = 0; j < 4; j++) { acc[j][0] = 0ULL; acc[j][1] = 0ULL; }
    const float4* lw4 = (const float4*)lw1;
    for (int kc = 0; kc < 4; kc++) {
#pragma unroll
        for (int it = 0; it < 4; it++) {
            int idx = tid + it * 256;
            int k = idx >> 5, c = idx & 31;
            ws4[k][c] = lw4[(kc * 32 + k) * 32 + c];
        }
#pragma unroll
        for (int j = 0; j < 4; j++)
            xsh[w][j][lane] = g_x0[(row0 + j) * HD + kc * 32 + lane];
        __syncthreads();
#pragma unroll
        for (int k = 0; k < 32; k++) {
            float4 wv = ws4[k][lane];
            unsigned long long wlo = pk2(wv.x, wv.y), whi = pk2(wv.z, wv.w);
#pragma unroll
            for (int j = 0; j < 4; j++) {
                float xv = xsh[w][j][k];
                unsigned long long x2 = pk2(xv, xv);
                fma2(acc[j][0], x2, wlo);
                fma2(acc[j][1], x2, whi);
            }
        }
        __syncthreads();
    }
    float4 bv = ((const float4*)b1)[lane];
#pragma unroll
    for (int j = 0; j < 4; j++) {
        int row = row0 + j;
        float4 av = ((const float4*)(g_agg1 + row * HD))[lane];
        float o0, o1, o2, o3;
        upk2(acc[j][0], o0, o1);
        upk2(acc[j][1], o2, o3);
        o0 = fmaxf(o0 + av.x + bv.x, 0.f);
        o1 = fmaxf(o1 + av.y + bv.y, 0.f);
        o2 = fmaxf(o2 + av.z + bv.z, 0.f);
        o3 = fmaxf(o3 + av.w + bv.w, 0.f);
        ((float4*)(g_out1 + row * HD))[lane] = make_float4(o0, o1, o2, o3);
    }
}

// ---------------- 4) layer2 edge messages: warp walks EPW sorted edges, 2 at a time ------
__global__ __launch_bounds__(256) void edge2_kernel(const float* __restrict__ W2) {
    int warp = (blockIdx.x * 256 + threadIdx.x) >> 5;
    int lane = threadIdx.x & 31;
    int e0 = warp * EPW;
    int cur = -1;
    float4 wA, wB, wC, wD;
    int4 r0 = __ldg(&g_recs[e0]);
    int4 r1 = __ldg(&g_recs[e0 + 1]);
#pragma unroll 1
    for (int e = 0; e < EPW; e += 2) {
        int4 n0 = r0, n1 = r1;
        if (e + 2 < EPW) {
            n0 = __ldg(&g_recs[e0 + e + 2]);
            n1 = __ldg(&g_recs[e0 + e + 3]);
        }
        float4 xv0 = ((const float4*)(g_out1 + r0.x * HD))[lane];
        float4 xv1 = ((const float4*)(g_out1 + r1.x * HD))[lane];
        float nrm0 = __int_as_float(r0.w), nrm1 = __int_as_float(r1.w);
        if (r0.z != cur) {
            const float4* w4 = (const float4*)(W2 + r0.z * 512 + lane * 16);
            wA = __ldg(w4); wB = __ldg(w4 + 1); wC = __ldg(w4 + 2); wD = __ldg(w4 + 3);
            cur = r0.z;
        }
        {
            float l0 = (xv0.x * wA.x + xv0.y * wB.x) * nrm0;
            float l1 = (xv0.x * wA.y + xv0.y * wB.y) * nrm0;
            float l2 = (xv0.x * wA.z + xv0.y * wB.z) * nrm0;
            float l3 = (xv0.x * wA.w + xv0.y * wB.w) * nrm0;
            float h0 = (xv0.z * wC.x + xv0.w * wD.x) * nrm0;
            float h1 = (xv0.z * wC.y + xv0.w * wD.y) * nrm0;
            float h2 = (xv0.z * wC.z + xv0.w * wD.z) * nrm0;
            float h3 = (xv0.z * wC.w + xv0.w * wD.w) * nrm0;
            float* base = g_agg2 + r0.y * 2 * HD + lane * 8;
            red_add_v4(base, l0, l1, l2, l3);
            red_add_v4(base + 4, h0, h1, h2, h3);
        }
        if (r1.z != cur) {
            const float4* w4 = (const float4*)(W2 + r1.z * 512 + lane * 16);
            wA = __ldg(w4); wB = __ldg(w4 + 1); wC = __ldg(w4 + 2); wD = __ldg(w4 + 3);
            cur = r1.z;
        }
        {
            float l0 = (xv1.x * wA.x + xv1.y * wB.x) * nrm1;
            float l1 = (xv1.x * wA.y + xv1.y * wB.y) * nrm1;
            float l2 = (xv1.x * wA.z + xv1.y * wB.z) * nrm1;
            float l3 = (xv1.x * wA.w + xv1.y * wB.w) * nrm1;
            float h0 = (xv1.z * wC.x + xv1.w * wD.x) * nrm1;
            float h1 = (xv1.z * wC.y + xv1.w * wD.y) * nrm1;
            float h2 = (xv1.z * wC.z + xv1.w * wD.z) * nrm1;
            float h3 = (xv1.z * wC.w + xv1.w * wD.w) * nrm1;
            float* base = g_agg2 + r1.y * 2 * HD + lane * 8;
            red_add_v4(base, l0, l1, l2, l3);
            red_add_v4(base + 4, h0, h1, h2, h3);
        }
        r0 = n0; r1 = n1;
    }
}

// ---------------- 5) self-loop layer2 + gaussian sample + bf16 split, fused ----------------
__global__ __launch_bounds__(256) void selfloop2_kernel(const float* __restrict__ lw2,
                                                        const float* __restrict__ b2,
                                                        const float* __restrict__ eps) {
    __shared__ float4 ws4[32][64];
    __shared__ float xsh[8][4][33];
    int tid = threadIdx.x;
    int w = tid >> 5, lane = tid & 31;
    int row0 = blockIdx.x * 32 + w * 4;
    unsigned long long acc[4][4];
#pragma unroll
    for (int j = 0; j < 4; j++)
#pragma unroll
        for (int g = 0; g < 4; g++) acc[j][g] = 0ULL;
    const float4* lw4 = (const float4*)lw2;
    for (int kc = 0; kc < 4; kc++) {
#pragma unroll
        for (int it = 0; it < 8; it++) {
            int idx = tid + it * 256;
            int k = idx >> 6, c = idx & 63;
            ws4[k][c] = lw4[(kc * 32 + k) * 64 + c];
        }
#pragma unroll
        for (int j = 0; j < 4; j++)
            xsh[w][j][lane] = g_out1[(row0 + j) * HD + kc * 32 + lane];
        __syncthreads();
#pragma unroll
        for (int k = 0; k < 32; k++) {
            float4 w0 = ws4[k][lane];
            float4 w1 = ws4[k][32 + lane];
            unsigned long long wl0 = pk2(w0.x, w0.y), wh0 = pk2(w0.z, w0.w);
            unsigned long long wl1 = pk2(w1.x, w1.y), wh1 = pk2(w1.z, w1.w);
#pragma unroll
            for (int j = 0; j < 4; j++) {
                float xv = xsh[w][j][k];
                unsigned long long x2 = pk2(xv, xv);
                fma2(acc[j][0], x2, wl0);
                fma2(acc[j][1], x2, wh0);
                fma2(acc[j][2], x2, wl1);
                fma2(acc[j][3], x2, wh1);
            }
        }
        __syncthreads();
    }
    float4 b0 = ((const float4*)b2)[lane];
    float4 b1v = ((const float4*)b2)[32 + lane];
#pragma unroll
    for (int j = 0; j < 4; j++) {
        int row = row0 + j;
        float4 a0 = ((const float4*)(g_agg2 + row * 2 * HD))[lane];
        float4 a1 = ((const float4*)(g_agg2 + row * 2 * HD))[32 + lane];
        float m0, m1, m2, m3, v0, v1, v2, v3;
        upk2(acc[j][0], m0, m1);
        upk2(acc[j][1], m2, m3);
        upk2(acc[j][2], v0, v1);
        upk2(acc[j][3], v2, v3);
        m0 += a0.x + b0.x; m1 += a0.y + b0.y; m2 += a0.z + b0.z; m3 += a0.w + b0.w;
        v0 += a1.x + b1v.x; v1 += a1.y + b1v.y; v2 += a1.z + b1v.z; v3 += a1.w + b1v.w;
        float4 ev = ((const float4*)(eps + row * HD))[lane];
        float z0 = m0 + sqrtf(softplus_f(v0) + 1e-8f) * ev.x;
        float z1 = m1 + sqrtf(softplus_f(v1) + 1e-8f) * ev.y;
        float z2 = m2 + sqrtf(softplus_f(v2) + 1e-8f) * ev.z;
        float z3 = m3 + sqrtf(softplus_f(v3) + 1e-8f) * ev.w;
        ((float4*)(g_z + row * HD))[lane] = make_float4(z0, z1, z2, z3);
        // split to bf16 hi/lo for the tensor-core decoder
        __nv_bfloat16 h0b = __float2bfloat16(z0), h1b = __float2bfloat16(z1);
        __nv_bfloat16 h2b = __float2bfloat16(z2), h3b = __float2bfloat16(z3);
        __nv_bfloat16 l0b = __float2bfloat16(z0 - __bfloat162float(h0b));
        __nv_bfloat16 l1b = __float2bfloat16(z1 - __bfloat162float(h1b));
        __nv_bfloat16 l2b = __float2bfloat16(z2 - __bfloat162float(h2b));
        __nv_bfloat16 l3b = __float2bfloat16(z3 - __bfloat162float(h3b));
        __nv_bfloat162* zh = (__nv_bfloat162*)(g_zhi + row * HD);
        __nv_bfloat162* zl = (__nv_bfloat162*)(g_zlo + row * HD);
        zh[lane * 2]     = __nv_bfloat162(h0b, h1b);
        zh[lane * 2 + 1] = __nv_bfloat162(h2b, h3b);
        zl[lane * 2]     = __nv_bfloat162(l0b, l1b);
        zl[lane * 2 + 1] = __nv_bfloat162(l2b, l3b);
    }
}

// ---------------- 6) hr = z[head_ids] * w_rel[rel_ids], split to bf16 hi/lo ----------------
__global__ __launch_bounds__(256) void hr_kernel(const int* __restrict__ head_ids,
                                                 const int* __restrict__ rel_ids,
                                                 const float* __restrict__ w_rel) {
    int idx = blockIdx.x * blockDim.x + threadIdx.x;  // 0 .. 2048*128-1
    int b = idx >> 7, c = idx & 127;
    float v = g_z[head_ids[b] * HD + c] * w_rel[rel_ids[b] * HD + c];
    __nv_bfloat16 hi = __float2bfloat16(v);
    g_hrhi[idx] = hi;
    g_hrlo[idx] = __float2bfloat16(v - __bfloat162float(hi));
}

// ---------------- 7) decoder via mma.sync bf16 (split-bf16, K-chunked, 2 CTAs/SM) -------
#define TROW 144
#define TILE_SB (128 * TROW)              // 18432 B per tile
#define DEC_SMEM (4 * TILE_SB)            // 73728 B

__global__ __launch_bounds__(256, 2) void decoder_mma_kernel(float* __restrict__ out) {
    extern __shared__ char smem[];
    char* sAhi = smem;
    char* sAlo = smem + TILE_SB;
    char* sBhi = smem + 2 * TILE_SB;
    char* sBlo = smem + 3 * TILE_SB;
    int tid = threadIdx.x;
    int wid = tid >> 5, lane = tid & 31;
    int col0 = blockIdx.x * 128;   // N tile (z rows), 157 tiles, last partial
    int row0 = blockIdx.y * 128;   // M tile (hr rows), exact

    int wr = wid & 1, wc = wid >> 1;
    float acc[4][4][4];
#pragma unroll
    for (int mi = 0; mi < 4; mi++)
#pragma unroll
        for (int ni = 0; ni < 4; ni++)
#pragma unroll
            for (int x = 0; x < 4; x++) acc[mi][ni][x] = 0.f;

    // per-lane ldmatrix base addresses
    int aRow = wr * 64 + (lane & 7) + ((lane >> 3) & 1) * 8;
    int aKoff = ((lane >> 4) & 1) * 16;
    uint32_t aBaseHi = smem_to_u32(sAhi) + aRow * TROW + aKoff;
    uint32_t aBaseLo = smem_to_u32(sAlo) + aRow * TROW + aKoff;
    int bRow = wc * 32 + (lane & 7);
    int bKoff = ((lane >> 3) & 1) * 16;
    uint32_t bBaseHi = smem_to_u32(sBhi) + bRow * TROW + bKoff;
    uint32_t bBaseLo = smem_to_u32(sBlo) + bRow * TROW + bKoff;

    const __nv_bfloat16* srcs[4] = {g_hrhi, g_hrlo, g_zhi, g_zlo};
    char* dsts[4] = {sAhi, sAlo, sBhi, sBlo};

#pragma unroll 1
    for (int kc = 0; kc < 2; kc++) {
        // ---- load 4 tiles of this K-chunk: 128 rows x 128B each ----
#pragma unroll
        for (int t = 0; t < 4; t++) {
            bool isB = (t >= 2);
            const __nv_bfloat16* src = srcs[t];
            char* dst = dsts[t];
#pragma unroll
            for (int it = 0; it < 4; it++) {
                int idx = tid + it * 256;       // 0..1023
                int r = idx >> 3, q = idx & 7;  // row, 16B chunk
                uint4 v = make_uint4(0u, 0u, 0u, 0u);
                int grow = (isB ? col0 : row0) + r;
                if (!isB || grow < NN)
                    v = *(const uint4*)(src + grow * HD + kc * 64 + q * 8);
                *(uint4*)(dst + r * TROW + q * 16) = v;
            }
        }
        __syncthreads();

        // ---- 4 k16-steps over this chunk ----
#pragma unroll
        for (int ks = 0; ks < 4; ks++) {
            int ko = ks * 32;   // 16 bf16 = 32 bytes per k-step
            uint32_t bh[4][2], bl[4][2];
#pragma unroll
            for (int ni = 0; ni < 4; ni++) {
                ldm_x2(bh[ni][0], bh[ni][1], bBaseHi + ni * 8 * TROW + ko);
                ldm_x2(bl[ni][0], bl[ni][1], bBaseLo + ni * 8 * TROW + ko);
            }
#pragma unroll
            for (int mi = 0; mi < 4; mi++) {
                uint32_t ah0, ah1, ah2, ah3, al0, al1, al2, al3;
                ldm_x4(ah0, ah1, ah2, ah3, aBaseHi + mi * 16 * TROW + ko);
                ldm_x4(al0, al1, al2, al3, aBaseLo + mi * 16 * TROW + ko);
#pragma unroll
                for (int ni = 0; ni < 4; ni++) {
                    mma_bf16(acc[mi][ni], ah0, ah1, ah2, ah3, bh[ni][0], bh[ni][1]);
                    mma_bf16(acc[mi][ni], ah0, ah1, ah2, ah3, bl[ni][0], bl[ni][1]);
                    mma_bf16(acc[mi][ni], al0, al1, al2, al3, bh[ni][0], bh[ni][1]);
                }
            }
        }
        __syncthreads();
    }

    // ---- store: lane l owns (m = l>>2 [+8], n = (l&3)*2 [,+1]) per atom ----
#pragma unroll
    for (int mi = 0; mi < 4; mi++) {
        int rgA = row0 + wr * 64 + mi * 16 + (lane >> 2);
        float* orow0 = out + (size_t)rgA * NN;
        float* orow1 = out + (size_t)(rgA + 8) * NN;
#pragma unroll
        for (int ni = 0; ni < 4; ni++) {
            int cg = col0 + wc * 32 + ni * 8 + (lane & 3) * 2;
            if (cg < NN) {   // NN even, (cg, cg+1) valid together
                *(float2*)(orow0 + cg) = make_float2(acc[mi][ni][0], acc[mi][ni][1]);
                *(float2*)(orow1 + cg) = make_float2(acc[mi][ni][2], acc[mi][ni][3]);
            }
        }
    }
}

// ---------------- launch ----------------
extern "C" void kernel_launch(void* const* d_in, const int* in_sizes, int n_in,
                              void* d_out, int out_size) {
    const int*   h        = (const int*)d_in[0];
    const int*   src      = (const int*)d_in[1];
    const int*   dst      = (const int*)d_in[2];
    const int*   etypes   = (const int*)d_in[3];
    const float* norm     = (const float*)d_in[4];
    const int*   head_ids = (const int*)d_in[5];
    const int*   rel_ids  = (const int*)d_in[6];
    const float* embed    = (const float*)d_in[7];
    const float* W1       = (const float*)d_in[8];
    const float* lw1      = (const float*)d_in[9];
    const float* b1       = (const float*)d_in[10];
    const float* W2       = (const float*)d_in[11];
    const float* lw2      = (const float*)d_in[12];
    const float* b2       = (const float*)d_in[13];
    const float* w_rel    = (const float*)d_in[14];
    const float* eps      = (const float*)d_in[15];
    float* out = (float*)d_out;

    cudaFuncSetAttribute(decoder_mma_kernel,
                         cudaFuncAttributeMaxDynamicSharedMemorySize, DEC_SMEM);

    init_kernel<<<(NN * 2 * HD) / 256, 256>>>(h, embed);
    hist_kernel<<<EE / 1024, 256>>>(etypes);
    scan_kernel<<<1, 128>>>();
    scatter_kernel<<<EE / 1024, 256>>>(src, dst, etypes, norm);
    edge1_kernel<<<EE / (EPW * 8), 256>>>(W1);
    selfloop1_kernel<<<NN / 32, 256>>>(lw1, b1);
    edge2_kernel<<<EE / (EPW * 8), 256>>>(W2);
    selfloop2_kernel<<<NN / 32, 256>>>(lw2, b2, eps);
    hr_kernel<<<(2048 * HD) / 256, 256>>>(head_ids, rel_ids, w_rel);
    dim3 dgrid((NN + 127) / 128, 2048 / 128);
    decoder_mma_kernel<<<dgrid, 256, DEC_SMEM>>>(out);
}